// round 1
// baseline (speedup 1.0000x reference)
#include <cuda_runtime.h>
#include <cstdint>

#define NUSERS 100000
#define NITEMS 50000
#define EMBED 64
#define RREL 3
#define NNZ_E 1000000
#define IG_NNZ_E 500000
#define BB 512
#define KK 100
#define EPSF 1e-8f
#define SCORE2_SCALE (0.5f/3.0f)
#define L2C 1e-4f

// ---------------- device scratch (static, allocation-free) ----------------
__device__ __align__(16) float g_item_agg[NITEMS*EMBED];
__device__ __align__(16) float g_item_prop[NITEMS*EMBED];
__device__ __align__(16) float g_item_feat[NITEMS*EMBED];
__device__ __align__(16) float g_item_featW[NITEMS*EMBED];
__device__ float g_ig_deg[NITEMS];
__device__ int   g_map[NUSERS];
__device__ float g_udeg[BB];
__device__ float g_utotal[BB];
__device__ __align__(16) float g_uacc[BB*2*EMBED];
__device__ __align__(16) float g_ufpartial[BB*EMBED];
__device__ __align__(16) float g_proj[BB*2*EMBED];
__device__ __align__(16) float g_u2[BB*EMBED];
__device__ double g_l2i;
__device__ double g_l2u;

__device__ __forceinline__ void red_add_v4(float* addr, float4 v) {
    asm volatile("red.global.add.v4.f32 [%0], {%1,%2,%3,%4};"
                 :: "l"(addr), "f"(v.x), "f"(v.y), "f"(v.z), "f"(v.w) : "memory");
}

// ---------------- init / zero ----------------
__global__ void k_zero_pre(float* __restrict__ out, int out_n) {
    int idx = blockIdx.x * blockDim.x + threadIdx.x;
    if (idx < NITEMS*EMBED) g_item_feat[idx] = 0.0f;
    if (idx < NUSERS)       g_map[idx] = -1;
    if (idx < BB*EMBED)     g_ufpartial[idx] = 0.0f;
    if (idx < BB)           g_utotal[idx] = 0.0f;
    if (idx < out_n)        out[idx] = 0.0f;
    if (idx == 0) { g_l2i = 0.0; g_l2u = 0.0; }
}

__global__ void k_zero_rel() {
    int idx = blockIdx.x * blockDim.x + threadIdx.x;
    if (idx < NITEMS*EMBED) g_item_agg[idx] = 0.0f;
    if (idx < NITEMS)       g_ig_deg[idx] = 0.0f;
    if (idx < BB*2*EMBED)   g_uacc[idx] = 0.0f;
    if (idx < BB)           g_udeg[idx] = 0.0f;
}

__global__ void k_map(const int* __restrict__ user) {
    int b = threadIdx.x;  // 512 threads, 1 block
    if (b < BB) g_map[user[b]] = b;   // dup uids: any winner is consistent
}

// ---------------- item-graph aggregation (scatter) ----------------
__global__ void k_ig(const int* __restrict__ rows, const int* __restrict__ cols,
                     const float* __restrict__ vals, const float* __restrict__ item_emb) {
    int gtid = blockIdx.x * blockDim.x + threadIdx.x;
    int e = gtid >> 4;
    if (e >= IG_NNZ_E) return;
    int p = gtid & 15;
    int row = rows[e];
    int col = cols[e];
    float v = vals[e];
    float4 x = reinterpret_cast<const float4*>(item_emb)[col*16 + p];
    x.x *= v; x.y *= v; x.z *= v; x.w *= v;
    red_add_v4(&g_item_agg[row*EMBED + p*4], x);
    if (p == 0) atomicAdd(&g_ig_deg[row], v);
}

// ---------------- train graph scatter: item_feature ----------------
__global__ void k_train(const int* __restrict__ rows, const int* __restrict__ cols,
                        const float* __restrict__ user_emb) {
    int gtid = blockIdx.x * blockDim.x + threadIdx.x;
    int e = gtid >> 4;
    if (e >= NNZ_E) return;
    int p = gtid & 15;
    int row = rows[e];
    int col = cols[e];
    float4 x = reinterpret_cast<const float4*>(user_emb)[row*16 + p];
    red_add_v4(&g_item_feat[col*EMBED + p*4], x);
}

// ---------------- (NITEMS x 64) @ (64 x 64), optional row-normalize ----------------
__global__ void k_matmul64(const float* __restrict__ A, const float* __restrict__ Wm,
                           const float* __restrict__ deg, float* __restrict__ Out, int nrows) {
    __shared__ float4 w_s[64*16];   // W[k][4j..4j+3]
    __shared__ float4 a_s[16*16];
    int tid = threadIdx.x;          // 256
    const float4* W4 = reinterpret_cast<const float4*>(Wm);
    for (int t = tid; t < 64*16; t += 256) w_s[t] = W4[t];
    __syncthreads();
    int r = tid >> 4, j = tid & 15;
    int nchunks = nrows / 16;
    for (int chunk = blockIdx.x; chunk < nchunks; chunk += gridDim.x) {
        int row0 = chunk * 16;
        {
            int row = row0 + r;
            float4 v = reinterpret_cast<const float4*>(A)[row*16 + j];
            if (deg) {
                float inv = 1.0f / (deg[row] + EPSF);
                v.x *= inv; v.y *= inv; v.z *= inv; v.w *= inv;
            }
            a_s[r*16 + j] = v;
        }
        __syncthreads();
        float4 acc = make_float4(0.f,0.f,0.f,0.f);
        #pragma unroll
        for (int kk = 0; kk < 16; kk++) {
            float4 a  = a_s[r*16 + kk];
            float4 w0 = w_s[(4*kk+0)*16 + j];
            float4 w1 = w_s[(4*kk+1)*16 + j];
            float4 w2 = w_s[(4*kk+2)*16 + j];
            float4 w3 = w_s[(4*kk+3)*16 + j];
            acc.x += a.x*w0.x + a.y*w1.x + a.z*w2.x + a.w*w3.x;
            acc.y += a.x*w0.y + a.y*w1.y + a.z*w2.y + a.w*w3.y;
            acc.z += a.x*w0.z + a.y*w1.z + a.z*w2.z + a.w*w3.z;
            acc.w += a.x*w0.w + a.y*w1.w + a.z*w2.w + a.w*w3.w;
        }
        reinterpret_cast<float4*>(Out)[(row0 + r)*16 + j] = acc;
        __syncthreads();
    }
}

// ---------------- rel-edge filter + per-slot 128-dim accumulation ----------------
__global__ void k_rel(const int* __restrict__ rows, const int* __restrict__ cols,
                      const float* __restrict__ item_emb) {
    int e = blockIdx.x * blockDim.x + threadIdx.x;
    if (e >= NNZ_E) return;
    int row = rows[e];
    int slot = g_map[row];
    if (slot < 0) return;
    atomicAdd(&g_udeg[slot], 1.0f);
    int col = cols[e];
    const float4* ie = reinterpret_cast<const float4*>(item_emb) + col*16;
    const float4* ip = reinterpret_cast<const float4*>(g_item_prop) + col*16;
    float* dst = g_uacc + slot*128;
    #pragma unroll
    for (int t = 0; t < 16; t++) red_add_v4(dst + 4*t, ie[t]);
    #pragma unroll
    for (int t = 0; t < 16; t++) red_add_v4(dst + 64 + 4*t, ip[t]);
}

// ---------------- fold relation into user_feature partial ----------------
__global__ void k_user_update(const float* __restrict__ mgnn, int i) {
    int idx = blockIdx.x * blockDim.x + threadIdx.x;
    if (idx >= BB*EMBED) return;
    int slot = idx >> 6, d = idx & 63;
    float deg = g_udeg[slot];
    float m = mgnn[i];
    float c = m * deg / (deg + EPSF);
    g_ufpartial[idx] += c * g_uacc[slot*128 + d];
    if (d == 0) g_utotal[slot] += m * deg;
}

// ---------------- proj = (acc/(deg+eps)) @ Wb_i  (512 x 128 @ 128x128) ----------------
__global__ void k_proj(const float* __restrict__ Wb) {
    __shared__ float a_s[128];
    int slot = blockIdx.x, j = threadIdx.x;   // 512 blocks x 128 thr
    float inv = 1.0f / (g_udeg[slot] + EPSF);
    a_s[j] = g_uacc[slot*128 + j] * inv;
    __syncthreads();
    float acc = 0.f;
    #pragma unroll 8
    for (int k = 0; k < 128; k++) acc += a_s[k] * Wb[k*128 + j];
    g_proj[slot*128 + j] = acc;
}

// ---------------- score2 accumulation ----------------
__global__ void k_score2(const int* __restrict__ user, const int* __restrict__ item,
                         const float* __restrict__ item_emb, float* __restrict__ out) {
    int idx = blockIdx.x * blockDim.x + threadIdx.x;
    if (idx >= BB*KK) return;
    int b = idx / KK;
    int slot = g_map[user[b]];
    int it = item[idx];
    const float4* pr = reinterpret_cast<const float4*>(g_proj) + slot*32;
    const float4* ie = reinterpret_cast<const float4*>(item_emb) + it*16;
    const float4* ip = reinterpret_cast<const float4*>(g_item_prop) + it*16;
    float s = 0.f;
    #pragma unroll
    for (int t = 0; t < 16; t++) {
        float4 a = pr[t], c = ie[t];
        s += a.x*c.x + a.y*c.y + a.z*c.z + a.w*c.w;
    }
    #pragma unroll
    for (int t = 0; t < 16; t++) {
        float4 a = pr[16 + t], c = ip[t];
        s += a.x*c.x + a.y*c.y + a.z*c.z + a.w*c.w;
    }
    out[idx] += SCORE2_SCALE * s;
}

// ---------------- u2 = (ufpartial/(total+eps)) @ W ----------------
__global__ void k_userW(const float* __restrict__ Wm) {
    __shared__ float a_s[64];
    int slot = blockIdx.x, j = threadIdx.x;   // 512 blocks x 64 thr
    float inv = 1.0f / (g_utotal[slot] + EPSF);
    a_s[j] = g_ufpartial[slot*64 + j] * inv;
    __syncthreads();
    float acc = 0.f;
    #pragma unroll 8
    for (int k = 0; k < 64; k++) acc += a_s[k] * Wm[k*64 + j];
    g_u2[slot*64 + j] = acc;
}

// ---------------- score1 + item-side L2 ----------------
__global__ void k_score1(const int* __restrict__ user, const int* __restrict__ item,
                         const float* __restrict__ user_emb, const float* __restrict__ item_emb,
                         float* __restrict__ out) {
    int idx = blockIdx.x * blockDim.x + threadIdx.x;
    float n2 = 0.f;
    if (idx < BB*KK) {
        int b = idx / KK;
        int uid = user[b];
        int slot = g_map[uid];
        int it = item[idx];
        const float4* ue  = reinterpret_cast<const float4*>(user_emb) + uid*16;
        const float4* u2  = reinterpret_cast<const float4*>(g_u2) + slot*16;
        const float4* ie  = reinterpret_cast<const float4*>(item_emb) + it*16;
        const float4* ifw = reinterpret_cast<const float4*>(g_item_featW) + it*16;
        float s = 0.f;
        #pragma unroll
        for (int t = 0; t < 16; t++) {
            float4 a = ue[t], c = ie[t];
            s  += a.x*c.x + a.y*c.y + a.z*c.z + a.w*c.w;
            n2 += c.x*c.x + c.y*c.y + c.z*c.z + c.w*c.w;
        }
        #pragma unroll
        for (int t = 0; t < 16; t++) {
            float4 a = u2[t], c = ifw[t];
            s  += a.x*c.x + a.y*c.y + a.z*c.z + a.w*c.w;
            n2 += c.x*c.x + c.y*c.y + c.z*c.z + c.w*c.w;
        }
        out[idx] += s;
    }
    __shared__ float red[256];
    red[threadIdx.x] = n2;
    __syncthreads();
    for (int s = 128; s > 0; s >>= 1) {
        if (threadIdx.x < s) red[threadIdx.x] += red[threadIdx.x + s];
        __syncthreads();
    }
    if (threadIdx.x == 0) atomicAdd(&g_l2i, (double)red[0]);
}

// ---------------- user-side L2 (single block) ----------------
__global__ void k_l2u(const int* __restrict__ user, const float* __restrict__ user_emb) {
    int b = threadIdx.x;   // 512
    float n2 = 0.f;
    int uid = user[b];
    int slot = g_map[uid];
    const float4* ue = reinterpret_cast<const float4*>(user_emb) + uid*16;
    const float4* u2 = reinterpret_cast<const float4*>(g_u2) + slot*16;
    #pragma unroll
    for (int t = 0; t < 16; t++) {
        float4 a = ue[t]; n2 += a.x*a.x + a.y*a.y + a.z*a.z + a.w*a.w;
        float4 c = u2[t]; n2 += c.x*c.x + c.y*c.y + c.z*c.z + c.w*c.w;
    }
    __shared__ float red[512];
    red[b] = n2;
    __syncthreads();
    for (int s = 256; s > 0; s >>= 1) {
        if (b < s) red[b] += red[b + s];
        __syncthreads();
    }
    if (b == 0) g_l2u = (double)red[0];
}

__global__ void k_final(float* __restrict__ out, int out_n) {
    if (threadIdx.x == 0 && out_n > BB*KK) {
        out[BB*KK] = (float)((double)L2C * ((double)KK * g_l2u + g_l2i));
    }
}

// ---------------- launch ----------------
extern "C" void kernel_launch(void* const* d_in, const int* in_sizes, int n_in,
                              void* d_out, int out_size) {
    const int*   user       = (const int*)  d_in[0];
    const int*   item       = (const int*)  d_in[1];
    const int*   rel_rows   = (const int*)  d_in[2];
    const int*   rel_cols   = (const int*)  d_in[3];
    const int*   ig_rows    = (const int*)  d_in[4];
    const int*   ig_cols    = (const int*)  d_in[5];
    const float* ig_vals    = (const float*)d_in[6];
    const int*   train_rows = (const int*)  d_in[7];
    const int*   train_cols = (const int*)  d_in[8];
    const float* user_emb   = (const float*)d_in[9];
    const float* item_emb   = (const float*)d_in[10];
    const float* mgnn       = (const float*)d_in[11];
    const float* Wb         = (const float*)d_in[12];
    const float* Wp         = (const float*)d_in[13];
    const float* Wm         = (const float*)d_in[14];
    float* out = (float*)d_out;

    float* p_item_agg;  cudaGetSymbolAddress((void**)&p_item_agg,  g_item_agg);
    float* p_item_prop; cudaGetSymbolAddress((void**)&p_item_prop, g_item_prop);
    float* p_item_feat; cudaGetSymbolAddress((void**)&p_item_feat, g_item_feat);
    float* p_item_featW;cudaGetSymbolAddress((void**)&p_item_featW,g_item_featW);
    float* p_ig_deg;    cudaGetSymbolAddress((void**)&p_ig_deg,    g_ig_deg);

    const int ZBLK = (NITEMS*EMBED + 255) / 256;   // 12500

    k_zero_pre<<<ZBLK, 256>>>(out, out_size);
    k_map<<<1, BB>>>(user);

    for (int i = 0; i < RREL; i++) {
        k_zero_rel<<<ZBLK, 256>>>();
        k_ig<<<(IG_NNZ_E*16 + 255)/256, 256>>>(ig_rows + (size_t)i*IG_NNZ_E,
                                               ig_cols + (size_t)i*IG_NNZ_E,
                                               ig_vals + (size_t)i*IG_NNZ_E, item_emb);
        k_matmul64<<<512, 256>>>(p_item_agg, Wp + (size_t)i*EMBED*EMBED,
                                 p_ig_deg, p_item_prop, NITEMS);
        k_rel<<<(NNZ_E + 255)/256, 256>>>(rel_rows + (size_t)i*NNZ_E,
                                          rel_cols + (size_t)i*NNZ_E, item_emb);
        k_user_update<<<(BB*EMBED + 255)/256, 256>>>(mgnn, i);
        k_proj<<<BB, 128>>>(Wb + (size_t)i*2*EMBED*2*EMBED);
        k_score2<<<(BB*KK + 255)/256, 256>>>(user, item, item_emb, out);
    }

    k_train<<<(NNZ_E*16 + 255)/256, 256>>>(train_rows, train_cols, user_emb);
    k_matmul64<<<512, 256>>>(p_item_feat, Wm, nullptr, p_item_featW, NITEMS);
    k_userW<<<BB, EMBED>>>(Wm);
    k_score1<<<(BB*KK + 255)/256, 256>>>(user, item, user_emb, item_emb, out);
    k_l2u<<<1, BB>>>(user, user_emb);
    k_final<<<1, 32>>>(out, out_size);
}

// round 2
// speedup vs baseline: 1.3558x; 1.3558x over previous
#include <cuda_runtime.h>
#include <cstdint>

#define NUSERS 100000
#define NITEMS 50000
#define EMBED 64
#define RREL 3
#define NNZ_E 1000000
#define IG_NNZ_E 500000
#define BB 512
#define KK 100
#define EPSF 1e-8f
#define SCORE2_SCALE (0.5f/3.0f)
#define L2C 1e-4f

#define IE (NITEMS*EMBED)   // 3,200,000 floats per relation plane

// ---------------- device scratch (static, allocation-free) ----------------
__device__ __align__(16) float g_item_agg[RREL*IE];
__device__ __align__(16) float g_item_prop[RREL*IE];
__device__ __align__(16) float g_item_feat[IE];
__device__ __align__(16) float g_item_featW[IE];
__device__ __align__(16) float g_ig_deg[RREL*NITEMS];
__device__ __align__(16) int   g_map[NUSERS];
__device__ __align__(16) float g_udeg[RREL*BB];
__device__ __align__(16) float g_uacc[RREL*BB*128];
__device__ __align__(16) float g_proj[RREL*BB*128];
__device__ __align__(16) float g_u2[BB*EMBED];
__device__ double g_l2i;
__device__ double g_l2u;

__device__ __forceinline__ void red_add_v4(float* addr, float4 v) {
    asm volatile("red.global.add.v4.f32 [%0], {%1,%2,%3,%4};"
                 :: "l"(addr), "f"(v.x), "f"(v.y), "f"(v.z), "f"(v.w) : "memory");
}

// ---------------- one-shot zero ----------------
// Largest range: g_item_agg = 2.4M float4 -> 9375 blocks x 256
__global__ void k_zero(float* __restrict__ out, int out_n) {
    int idx = blockIdx.x * blockDim.x + threadIdx.x;
    float4 z4 = make_float4(0.f,0.f,0.f,0.f);
    if (idx < RREL*IE/4)      reinterpret_cast<float4*>(g_item_agg)[idx] = z4;
    if (idx < IE/4)           reinterpret_cast<float4*>(g_item_feat)[idx] = z4;
    if (idx < RREL*NITEMS/4)  reinterpret_cast<float4*>(g_ig_deg)[idx] = z4;
    if (idx < RREL*BB*128/4)  reinterpret_cast<float4*>(g_uacc)[idx] = z4;
    if (idx < RREL*BB)        g_udeg[idx] = 0.f;
    if (idx < NUSERS/4)       reinterpret_cast<int4*>(g_map)[idx] = make_int4(-1,-1,-1,-1);
    if (idx < out_n)          out[idx] = 0.f;
    if (idx == 0) { g_l2i = 0.0; g_l2u = 0.0; }
}

__global__ void k_map(const int* __restrict__ user) {
    int b = threadIdx.x;
    if (b < BB) g_map[user[b]] = b;
}

// ---------------- item-graph scatter, all relations, 4 edges / thread -------
__global__ void k_ig(const int* __restrict__ rows_all, const int* __restrict__ cols_all,
                     const float* __restrict__ vals_all, const float* __restrict__ item_emb) {
    int r = blockIdx.y;
    const int*   rows = rows_all + (size_t)r*IG_NNZ_E;
    const int*   cols = cols_all + (size_t)r*IG_NNZ_E;
    const float* vals = vals_all + (size_t)r*IG_NNZ_E;
    float* agg = g_item_agg + (size_t)r*IE;
    float* deg = g_ig_deg + (size_t)r*NITEMS;

    int t = blockIdx.x * blockDim.x + threadIdx.x;
    int g = t >> 4;
    if (g >= IG_NNZ_E/4) return;
    int p = t & 15;
    int e0 = g * 4;
    int4   c = *reinterpret_cast<const int4*>(cols + e0);
    int4  rr = *reinterpret_cast<const int4*>(rows + e0);
    float4 v = *reinterpret_cast<const float4*>(vals + e0);
    const float4* E = reinterpret_cast<const float4*>(item_emb);
    float4 x0 = E[(size_t)c.x*16 + p];
    float4 x1 = E[(size_t)c.y*16 + p];
    float4 x2 = E[(size_t)c.z*16 + p];
    float4 x3 = E[(size_t)c.w*16 + p];
    x0.x*=v.x; x0.y*=v.x; x0.z*=v.x; x0.w*=v.x;
    x1.x*=v.y; x1.y*=v.y; x1.z*=v.y; x1.w*=v.y;
    x2.x*=v.z; x2.y*=v.z; x2.z*=v.z; x2.w*=v.z;
    x3.x*=v.w; x3.y*=v.w; x3.z*=v.w; x3.w*=v.w;
    red_add_v4(agg + (size_t)rr.x*64 + p*4, x0);
    red_add_v4(agg + (size_t)rr.y*64 + p*4, x1);
    red_add_v4(agg + (size_t)rr.z*64 + p*4, x2);
    red_add_v4(agg + (size_t)rr.w*64 + p*4, x3);
    if (p == 0) {
        atomicAdd(deg + rr.x, v.x);
        atomicAdd(deg + rr.y, v.y);
        atomicAdd(deg + rr.z, v.z);
        atomicAdd(deg + rr.w, v.w);
    }
}

// ---------------- train-graph scatter, 4 edges / thread ----------------
__global__ void k_train(const int* __restrict__ rows, const int* __restrict__ cols,
                        const float* __restrict__ user_emb) {
    int t = blockIdx.x * blockDim.x + threadIdx.x;
    int g = t >> 4;
    if (g >= NNZ_E/4) return;
    int p = t & 15;
    int e0 = g * 4;
    int4 rr = *reinterpret_cast<const int4*>(rows + e0);
    int4 cc = *reinterpret_cast<const int4*>(cols + e0);
    const float4* E = reinterpret_cast<const float4*>(user_emb);
    float4 x0 = E[(size_t)rr.x*16 + p];
    float4 x1 = E[(size_t)rr.y*16 + p];
    float4 x2 = E[(size_t)rr.z*16 + p];
    float4 x3 = E[(size_t)rr.w*16 + p];
    red_add_v4(g_item_feat + (size_t)cc.x*64 + p*4, x0);
    red_add_v4(g_item_feat + (size_t)cc.y*64 + p*4, x1);
    red_add_v4(g_item_feat + (size_t)cc.z*64 + p*4, x2);
    red_add_v4(g_item_feat + (size_t)cc.w*64 + p*4, x3);
}

// ---------------- (nrows x 64) @ (64 x 64) body ----------------
__device__ __forceinline__ void matmul64_body(const float* __restrict__ A,
                                              const float* __restrict__ Wm,
                                              const float* __restrict__ deg,
                                              float* __restrict__ Out, int nrows) {
    __shared__ float4 w_s[64*16];
    __shared__ float4 a_s[16*16];
    int tid = threadIdx.x;          // 256
    const float4* W4 = reinterpret_cast<const float4*>(Wm);
    for (int t = tid; t < 64*16; t += 256) w_s[t] = W4[t];
    __syncthreads();
    int r = tid >> 4, j = tid & 15;
    int nchunks = nrows / 16;
    for (int chunk = blockIdx.x; chunk < nchunks; chunk += gridDim.x) {
        int row0 = chunk * 16;
        {
            int row = row0 + r;
            float4 v = reinterpret_cast<const float4*>(A)[row*16 + j];
            if (deg) {
                float inv = 1.0f / (deg[row] + EPSF);
                v.x *= inv; v.y *= inv; v.z *= inv; v.w *= inv;
            }
            a_s[r*16 + j] = v;
        }
        __syncthreads();
        float4 acc = make_float4(0.f,0.f,0.f,0.f);
        #pragma unroll
        for (int kk = 0; kk < 16; kk++) {
            float4 a  = a_s[r*16 + kk];
            float4 w0 = w_s[(4*kk+0)*16 + j];
            float4 w1 = w_s[(4*kk+1)*16 + j];
            float4 w2 = w_s[(4*kk+2)*16 + j];
            float4 w3 = w_s[(4*kk+3)*16 + j];
            acc.x += a.x*w0.x + a.y*w1.x + a.z*w2.x + a.w*w3.x;
            acc.y += a.x*w0.y + a.y*w1.y + a.z*w2.y + a.w*w3.y;
            acc.z += a.x*w0.z + a.y*w1.z + a.z*w2.z + a.w*w3.z;
            acc.w += a.x*w0.w + a.y*w1.w + a.z*w2.w + a.w*w3.w;
        }
        reinterpret_cast<float4*>(Out)[(row0 + r)*16 + j] = acc;
        __syncthreads();
    }
}

// item_prop[r] = (item_agg[r]/deg[r]) @ Wp[r]   grid=(nb, RREL)
__global__ void k_matmul_prop(const float* __restrict__ Wp_all) {
    int r = blockIdx.y;
    matmul64_body(g_item_agg + (size_t)r*IE, Wp_all + (size_t)r*EMBED*EMBED,
                  g_ig_deg + (size_t)r*NITEMS, g_item_prop + (size_t)r*IE, NITEMS);
}

__global__ void k_matmul_featW(const float* __restrict__ Wm) {
    matmul64_body(g_item_feat, Wm, nullptr, g_item_featW, NITEMS);
}

// ---------------- rel-edge filter, 4 edges / thread, all relations ----------
__global__ void k_rel(const int* __restrict__ rows_all, const int* __restrict__ cols_all,
                      const float* __restrict__ item_emb) {
    int r = blockIdx.y;
    const int* rows = rows_all + (size_t)r*NNZ_E;
    const int* cols = cols_all + (size_t)r*NNZ_E;
    const float* prop = g_item_prop + (size_t)r*IE;
    int g = blockIdx.x * blockDim.x + threadIdx.x;
    if (g >= NNZ_E/4) return;
    int e0 = g * 4;
    int4 rr = *reinterpret_cast<const int4*>(rows + e0);
    int s0 = g_map[rr.x];
    int s1 = g_map[rr.y];
    int s2 = g_map[rr.z];
    int s3 = g_map[rr.w];
    #pragma unroll
    for (int q = 0; q < 4; q++) {
        int slot = (q==0)?s0:(q==1)?s1:(q==2)?s2:s3;
        if (slot < 0) continue;
        atomicAdd(&g_udeg[r*BB + slot], 1.0f);
        int col = cols[e0 + q];
        const float4* ie = reinterpret_cast<const float4*>(item_emb) + (size_t)col*16;
        const float4* ip = reinterpret_cast<const float4*>(prop) + (size_t)col*16;
        float* dst = g_uacc + ((size_t)r*BB + slot)*128;
        #pragma unroll
        for (int t = 0; t < 16; t++) red_add_v4(dst + 4*t, ie[t]);
        #pragma unroll
        for (int t = 0; t < 16; t++) red_add_v4(dst + 64 + 4*t, ip[t]);
    }
}

// ---------------- proj[r][slot] = (uacc/(deg+eps)) @ Wb[r]  grid=(BB,RREL)x128
__global__ void k_proj(const float* __restrict__ Wb_all) {
    __shared__ float a_s[128];
    int r = blockIdx.y, slot = blockIdx.x, j = threadIdx.x;
    const float* Wb = Wb_all + (size_t)r*128*128;
    float inv = 1.0f / (g_udeg[r*BB + slot] + EPSF);
    a_s[j] = g_uacc[((size_t)r*BB + slot)*128 + j] * inv;
    __syncthreads();
    float acc = 0.f;
    #pragma unroll 8
    for (int k = 0; k < 128; k++) acc += a_s[k] * Wb[k*128 + j];
    g_proj[((size_t)r*BB + slot)*128 + j] = acc;
}

// ---------------- u2 = user_feature @ W (folds weights/total)  512 x 64 -----
__global__ void k_userW(const float* __restrict__ Wm, const float* __restrict__ mgnn) {
    __shared__ float uf[64];
    int slot = blockIdx.x, j = threadIdx.x;
    float m0 = mgnn[0], m1 = mgnn[1], m2 = mgnn[2];
    float d0 = g_udeg[slot], d1 = g_udeg[BB+slot], d2 = g_udeg[2*BB+slot];
    float total = m0*d0 + m1*d1 + m2*d2;
    float c0 = m0*d0/(d0+EPSF), c1 = m1*d1/(d1+EPSF), c2 = m2*d2/(d2+EPSF);
    float v = c0*g_uacc[(size_t)slot*128 + j]
            + c1*g_uacc[((size_t)BB+slot)*128 + j]
            + c2*g_uacc[((size_t)2*BB+slot)*128 + j];
    uf[j] = v / (total + EPSF);
    __syncthreads();
    float acc = 0.f;
    #pragma unroll 8
    for (int k = 0; k < 64; k++) acc += uf[k] * Wm[k*64 + j];
    g_u2[slot*64 + j] = acc;
}

// ---------------- fused score1 + score2 + item L2 ----------------
__global__ void k_score(const int* __restrict__ user, const int* __restrict__ item,
                        const float* __restrict__ user_emb, const float* __restrict__ item_emb,
                        float* __restrict__ out) {
    int idx = blockIdx.x * blockDim.x + threadIdx.x;
    float n2 = 0.f;
    if (idx < BB*KK) {
        int b = idx / KK;
        int uid = user[b];
        int slot = g_map[uid];
        int it = item[idx];
        const float4* ue  = reinterpret_cast<const float4*>(user_emb) + (size_t)uid*16;
        const float4* u2  = reinterpret_cast<const float4*>(g_u2) + (size_t)slot*16;
        const float4* ie  = reinterpret_cast<const float4*>(item_emb) + (size_t)it*16;
        const float4* ifw = reinterpret_cast<const float4*>(g_item_featW) + (size_t)it*16;
        float s = 0.f;
        #pragma unroll
        for (int t = 0; t < 16; t++) {
            float4 a = ue[t], c = ie[t];
            s  += a.x*c.x + a.y*c.y + a.z*c.z + a.w*c.w;
            n2 += c.x*c.x + c.y*c.y + c.z*c.z + c.w*c.w;
        }
        #pragma unroll
        for (int t = 0; t < 16; t++) {
            float4 a = u2[t], c = ifw[t];
            s  += a.x*c.x + a.y*c.y + a.z*c.z + a.w*c.w;
            n2 += c.x*c.x + c.y*c.y + c.z*c.z + c.w*c.w;
        }
        float s2 = 0.f;
        #pragma unroll
        for (int r = 0; r < RREL; r++) {
            const float4* pr = reinterpret_cast<const float4*>(g_proj) + ((size_t)r*BB + slot)*32;
            const float4* ip = reinterpret_cast<const float4*>(g_item_prop + (size_t)r*IE) + (size_t)it*16;
            #pragma unroll
            for (int t = 0; t < 16; t++) {
                float4 a = pr[t], c = ie[t];
                s2 += a.x*c.x + a.y*c.y + a.z*c.z + a.w*c.w;
            }
            #pragma unroll
            for (int t = 0; t < 16; t++) {
                float4 a = pr[16+t], c = ip[t];
                s2 += a.x*c.x + a.y*c.y + a.z*c.z + a.w*c.w;
            }
        }
        out[idx] = s + SCORE2_SCALE * s2;
    }
    __shared__ float red[256];
    red[threadIdx.x] = n2;
    __syncthreads();
    for (int s = 128; s > 0; s >>= 1) {
        if (threadIdx.x < s) red[threadIdx.x] += red[threadIdx.x + s];
        __syncthreads();
    }
    if (threadIdx.x == 0) atomicAdd(&g_l2i, (double)red[0]);
}

// ---------------- user-side L2 ----------------
__global__ void k_l2u(const int* __restrict__ user, const float* __restrict__ user_emb) {
    int b = threadIdx.x;   // 512
    int uid = user[b];
    int slot = g_map[uid];
    const float4* ue = reinterpret_cast<const float4*>(user_emb) + (size_t)uid*16;
    const float4* u2 = reinterpret_cast<const float4*>(g_u2) + (size_t)slot*16;
    float n2 = 0.f;
    #pragma unroll
    for (int t = 0; t < 16; t++) {
        float4 a = ue[t]; n2 += a.x*a.x + a.y*a.y + a.z*a.z + a.w*a.w;
        float4 c = u2[t]; n2 += c.x*c.x + c.y*c.y + c.z*c.z + c.w*c.w;
    }
    __shared__ float red[512];
    red[b] = n2;
    __syncthreads();
    for (int s = 256; s > 0; s >>= 1) {
        if (b < s) red[b] += red[b + s];
        __syncthreads();
    }
    if (b == 0) g_l2u = (double)red[0];
}

__global__ void k_final(float* __restrict__ out, int out_n) {
    if (threadIdx.x == 0 && out_n > BB*KK) {
        out[BB*KK] = (float)((double)L2C * ((double)KK * g_l2u + g_l2i));
    }
}

// ---------------- launch ----------------
extern "C" void kernel_launch(void* const* d_in, const int* in_sizes, int n_in,
                              void* d_out, int out_size) {
    const int*   user       = (const int*)  d_in[0];
    const int*   item       = (const int*)  d_in[1];
    const int*   rel_rows   = (const int*)  d_in[2];
    const int*   rel_cols   = (const int*)  d_in[3];
    const int*   ig_rows    = (const int*)  d_in[4];
    const int*   ig_cols    = (const int*)  d_in[5];
    const float* ig_vals    = (const float*)d_in[6];
    const int*   train_rows = (const int*)  d_in[7];
    const int*   train_cols = (const int*)  d_in[8];
    const float* user_emb   = (const float*)d_in[9];
    const float* item_emb   = (const float*)d_in[10];
    const float* mgnn       = (const float*)d_in[11];
    const float* Wb         = (const float*)d_in[12];
    const float* Wp         = (const float*)d_in[13];
    const float* Wm         = (const float*)d_in[14];
    float* out = (float*)d_out;

    // zero: largest range is RREL*IE/4 = 2,400,000 float4
    k_zero<<<(RREL*IE/4 + 255)/256, 256>>>(out, out_size);
    k_map<<<1, BB>>>(user);

    // ig scatter: per relation 500K edges -> 125K groups * 16 threads = 2M
    {
        dim3 grid((IG_NNZ_E/4*16 + 255)/256, RREL);
        k_ig<<<grid, 256>>>(ig_rows, ig_cols, ig_vals, item_emb);
    }
    // train scatter: 1M edges -> 250K groups * 16 = 4M threads
    k_train<<<(NNZ_E/4*16 + 255)/256, 256>>>(train_rows, train_cols, user_emb);

    {
        dim3 grid(512, RREL);
        k_matmul_prop<<<grid, 256>>>(Wp);
    }
    k_matmul_featW<<<512, 256>>>(Wm);

    {
        dim3 grid((NNZ_E/4 + 255)/256, RREL);
        k_rel<<<grid, 256>>>(rel_rows, rel_cols, item_emb);
    }

    {
        dim3 grid(BB, RREL);
        k_proj<<<grid, 128>>>(Wb);
    }
    k_userW<<<BB, EMBED>>>(Wm, mgnn);

    k_score<<<(BB*KK + 255)/256, 256>>>(user, item, user_emb, item_emb, out);
    k_l2u<<<1, BB>>>(user, user_emb);
    k_final<<<1, 32>>>(out, out_size);
}

// round 3
// speedup vs baseline: 1.6314x; 1.2033x over previous
#include <cuda_runtime.h>
#include <cstdint>

#define NUSERS 100000
#define NITEMS 50000
#define EMBED 64
#define RREL 3
#define NNZ_E 1000000
#define IG_NNZ_E 500000
#define BB 512
#define KK 100
#define EPSF 1e-8f
#define SCORE2_SCALE (0.5f/3.0f)
#define L2C 1e-4f

#define IE (NITEMS*EMBED)        // 3,200,000 floats per relation plane
#define UBW 3200                 // user bitmap words (>= 100000/32)
#define IBW 1600                 // item bitmap words (>= 50000/32)

// ---------------- device scratch (static, allocation-free) ----------------
__device__ __align__(16) float g_item_agg[RREL*IE];
__device__ __align__(16) float g_item_feat[IE];
__device__ __align__(16) float g_item_featW[IE];
__device__ __align__(16) float g_ig_deg[RREL*NITEMS];
__device__ __align__(16) int   g_map[NUSERS];
__device__ __align__(16) unsigned g_ubit[UBW];   // batch-user bitmap
__device__ __align__(16) unsigned g_ibit[IBW];   // batch-item bitmap
__device__ __align__(16) unsigned g_nbit[IBW];   // "needed item_agg row" bitmap
__device__ __align__(16) float g_udeg[RREL*BB];
__device__ __align__(16) float g_uacc[RREL*BB*128];
__device__ __align__(16) float g_proj[RREL*BB*128];
__device__ __align__(16) float g_u2[BB*EMBED];
__device__ __align__(16) int2  g_crel[RREL*NNZ_E];   // compacted (slot,col)
__device__ __align__(16) int   g_ctrain[NNZ_E];      // compacted edge ids
__device__ int g_cnt_rel[RREL];
__device__ int g_cnt_train;
__device__ double g_l2i;
__device__ double g_l2u;

__device__ __forceinline__ void red_add_v4(float* addr, float4 v) {
    asm volatile("red.global.add.v4.f32 [%0], {%1,%2,%3,%4};"
                 :: "l"(addr), "f"(v.x), "f"(v.y), "f"(v.z), "f"(v.w) : "memory");
}

// ---------------- one-shot zero ----------------
__global__ void k_zero() {
    int idx = blockIdx.x * blockDim.x + threadIdx.x;
    float4 z4 = make_float4(0.f,0.f,0.f,0.f);
    if (idx < RREL*IE/4)       reinterpret_cast<float4*>(g_item_agg)[idx] = z4;
    if (idx < IE/4)            reinterpret_cast<float4*>(g_item_feat)[idx] = z4;
    if (idx < RREL*NITEMS/4)   reinterpret_cast<float4*>(g_ig_deg)[idx] = z4;
    if (idx < RREL*BB*128/4)   reinterpret_cast<float4*>(g_uacc)[idx] = z4;
    if (idx < RREL*BB)         g_udeg[idx] = 0.f;
    if (idx < NUSERS/4)        reinterpret_cast<int4*>(g_map)[idx] = make_int4(-1,-1,-1,-1);
    if (idx < UBW)             g_ubit[idx] = 0u;
    if (idx < IBW)             { g_ibit[idx] = 0u; g_nbit[idx] = 0u; }
    if (idx < RREL)            g_cnt_rel[idx] = 0;
    if (idx == 0)              { g_cnt_train = 0; g_l2i = 0.0; g_l2u = 0.0; }
}

// ---------------- build maps / bitmaps ----------------
__global__ void k_map(const int* __restrict__ user, const int* __restrict__ item) {
    int idx = blockIdx.x * blockDim.x + threadIdx.x;   // 51200 threads
    if (idx < BB) {
        int uid = user[idx];
        g_map[uid] = idx;                       // dup uids: any winner, data identical
        atomicOr(&g_ubit[uid >> 5], 1u << (uid & 31));
    }
    if (idx < BB*KK) {
        int it = item[idx];
        atomicOr(&g_ibit[it >> 5], 1u << (it & 31));
        atomicOr(&g_nbit[it >> 5], 1u << (it & 31));
    }
}

// ---------------- prescan rel edges: compact (slot, col) ----------------
__global__ void k_prescan_rel(const int* __restrict__ rows_all, const int* __restrict__ cols_all) {
    int r = blockIdx.y;
    const int* rows = rows_all + (size_t)r*NNZ_E;
    const int* cols = cols_all + (size_t)r*NNZ_E;
    int g = blockIdx.x * blockDim.x + threadIdx.x;
    if (g >= NNZ_E/4) return;
    int e0 = g * 4;
    int4 rr = *reinterpret_cast<const int4*>(rows + e0);
    #pragma unroll
    for (int q = 0; q < 4; q++) {
        int row = (q==0)?rr.x:(q==1)?rr.y:(q==2)?rr.z:rr.w;
        unsigned w = __ldg(&g_ubit[row >> 5]);
        if ((w >> (row & 31)) & 1u) {
            int slot = g_map[row];
            int col = __ldg(&cols[e0 + q]);
            int pos = atomicAdd(&g_cnt_rel[r], 1);
            g_crel[(size_t)r*NNZ_E + pos] = make_int2(slot, col);
            atomicAdd(&g_udeg[r*BB + slot], 1.0f);
            atomicOr(&g_nbit[col >> 5], 1u << (col & 31));
        }
    }
}

// ---------------- prescan train edges: compact passing edge ids ----------------
__global__ void k_prescan_train(const int* __restrict__ cols) {
    int g = blockIdx.x * blockDim.x + threadIdx.x;
    if (g >= NNZ_E/4) return;
    int e0 = g * 4;
    int4 cc = *reinterpret_cast<const int4*>(cols + e0);
    #pragma unroll
    for (int q = 0; q < 4; q++) {
        int col = (q==0)?cc.x:(q==1)?cc.y:(q==2)?cc.z:cc.w;
        unsigned w = __ldg(&g_ibit[col >> 5]);
        if ((w >> (col & 31)) & 1u) {
            int pos = atomicAdd(&g_cnt_train, 1);
            g_ctrain[pos] = e0 + q;
        }
    }
}

// ---------------- item-graph scatter (needed-rows only), 4 edges / thread ----
__global__ void k_ig(const int* __restrict__ rows_all, const int* __restrict__ cols_all,
                     const float* __restrict__ vals_all, const float* __restrict__ item_emb) {
    int r = blockIdx.y;
    const int*   rows = rows_all + (size_t)r*IG_NNZ_E;
    const int*   cols = cols_all + (size_t)r*IG_NNZ_E;
    const float* vals = vals_all + (size_t)r*IG_NNZ_E;
    float* agg = g_item_agg + (size_t)r*IE;
    float* deg = g_ig_deg + (size_t)r*NITEMS;

    int t = blockIdx.x * blockDim.x + threadIdx.x;
    int g = t >> 4;
    if (g >= IG_NNZ_E/4) return;
    int p = t & 15;
    int e0 = g * 4;
    int4  rr = *reinterpret_cast<const int4*>(rows + e0);
    int4   c = *reinterpret_cast<const int4*>(cols + e0);
    float4 v = *reinterpret_cast<const float4*>(vals + e0);
    const float4* E = reinterpret_cast<const float4*>(item_emb);
    bool n0 = (__ldg(&g_nbit[rr.x >> 5]) >> (rr.x & 31)) & 1u;
    bool n1 = (__ldg(&g_nbit[rr.y >> 5]) >> (rr.y & 31)) & 1u;
    bool n2 = (__ldg(&g_nbit[rr.z >> 5]) >> (rr.z & 31)) & 1u;
    bool n3 = (__ldg(&g_nbit[rr.w >> 5]) >> (rr.w & 31)) & 1u;
    if (n0) { float4 x = E[(size_t)c.x*16 + p]; x.x*=v.x; x.y*=v.x; x.z*=v.x; x.w*=v.x;
              red_add_v4(agg + (size_t)rr.x*64 + p*4, x); }
    if (n1) { float4 x = E[(size_t)c.y*16 + p]; x.x*=v.y; x.y*=v.y; x.z*=v.y; x.w*=v.y;
              red_add_v4(agg + (size_t)rr.y*64 + p*4, x); }
    if (n2) { float4 x = E[(size_t)c.z*16 + p]; x.x*=v.z; x.y*=v.z; x.z*=v.z; x.w*=v.z;
              red_add_v4(agg + (size_t)rr.z*64 + p*4, x); }
    if (n3) { float4 x = E[(size_t)c.w*16 + p]; x.x*=v.w; x.y*=v.w; x.z*=v.w; x.w*=v.w;
              red_add_v4(agg + (size_t)rr.w*64 + p*4, x); }
    if (p == 0) {
        if (n0) atomicAdd(deg + rr.x, v.x);
        if (n1) atomicAdd(deg + rr.y, v.y);
        if (n2) atomicAdd(deg + rr.z, v.z);
        if (n3) atomicAdd(deg + rr.w, v.w);
    }
}

// ---------------- train scatter over compacted list ----------------
__global__ void k_train(const int* __restrict__ rows, const int* __restrict__ cols,
                        const float* __restrict__ user_emb) {
    int t = blockIdx.x * blockDim.x + threadIdx.x;
    int g = t >> 4;
    int p = t & 15;
    int n = g_cnt_train;
    int base = g * 4;
    if (base >= n) return;
    int4 el = *reinterpret_cast<const int4*>(g_ctrain + base);
    const float4* E = reinterpret_cast<const float4*>(user_emb);
    #pragma unroll
    for (int q = 0; q < 4; q++) {
        if (base + q >= n) break;
        int e = (q==0)?el.x:(q==1)?el.y:(q==2)?el.z:el.w;
        int row = __ldg(&rows[e]);
        int col = __ldg(&cols[e]);
        float4 x = E[(size_t)row*16 + p];
        red_add_v4(g_item_feat + (size_t)col*64 + p*4, x);
    }
}

// ---------------- (nrows x 64) @ (64 x 64) ----------------
__global__ void k_matmul_featW(const float* __restrict__ Wm) {
    __shared__ float4 w_s[64*16];
    __shared__ float4 a_s[16*16];
    int tid = threadIdx.x;          // 256
    const float4* W4 = reinterpret_cast<const float4*>(Wm);
    for (int t = tid; t < 64*16; t += 256) w_s[t] = W4[t];
    __syncthreads();
    int r = tid >> 4, j = tid & 15;
    for (int chunk = blockIdx.x; chunk < NITEMS/16; chunk += gridDim.x) {
        int row0 = chunk * 16;
        a_s[r*16 + j] = reinterpret_cast<const float4*>(g_item_feat)[(row0 + r)*16 + j];
        __syncthreads();
        float4 acc = make_float4(0.f,0.f,0.f,0.f);
        #pragma unroll
        for (int kk = 0; kk < 16; kk++) {
            float4 a  = a_s[r*16 + kk];
            float4 w0 = w_s[(4*kk+0)*16 + j];
            float4 w1 = w_s[(4*kk+1)*16 + j];
            float4 w2 = w_s[(4*kk+2)*16 + j];
            float4 w3 = w_s[(4*kk+3)*16 + j];
            acc.x += a.x*w0.x + a.y*w1.x + a.z*w2.x + a.w*w3.x;
            acc.y += a.x*w0.y + a.y*w1.y + a.z*w2.y + a.w*w3.y;
            acc.z += a.x*w0.z + a.y*w1.z + a.z*w2.z + a.w*w3.z;
            acc.w += a.x*w0.w + a.y*w1.w + a.z*w2.w + a.w*w3.w;
        }
        reinterpret_cast<float4*>(g_item_featW)[(row0 + r)*16 + j] = acc;
        __syncthreads();
    }
}

// ---------------- heavy rel accumulation over compacted entries ----------------
// uacc[slot][0:64]  += item_emb[col]
// uacc[slot][64:128]+= item_agg[col]/(deg[col]+eps)     (Wp folded in later)
__global__ void k_rel_heavy(const float* __restrict__ item_emb) {
    int r = blockIdx.y;
    int ne = g_cnt_rel[r];
    const int2* lst = g_crel + (size_t)r*NNZ_E;
    const float4* agg4 = reinterpret_cast<const float4*>(g_item_agg + (size_t)r*IE);
    const float* deg = g_ig_deg + (size_t)r*NITEMS;
    int p = threadIdx.x & 15;
    int lane_entry = (blockIdx.x * blockDim.x + threadIdx.x) >> 4;
    int stride = (gridDim.x * blockDim.x) >> 4;
    for (int idx = lane_entry; idx < ne; idx += stride) {
        int2 ent = lst[idx];
        int slot = ent.x, col = ent.y;
        float4 ie = reinterpret_cast<const float4*>(item_emb)[(size_t)col*16 + p];
        float4 ag = agg4[(size_t)col*16 + p];
        float inv = 1.0f / (__ldg(&deg[col]) + EPSF);
        ag.x *= inv; ag.y *= inv; ag.z *= inv; ag.w *= inv;
        float* dst = g_uacc + ((size_t)r*BB + slot)*128;
        red_add_v4(dst + p*4, ie);
        red_add_v4(dst + 64 + p*4, ag);
    }
}

// ---------------- proj with Wp folding; outputs [proj1 | Wp@proj2] ----------------
__global__ void k_proj(const float* __restrict__ Wb_all, const float* __restrict__ Wp_all) {
    __shared__ float s_in[128], s_mid[128], s_pr[128];
    int r = blockIdx.y, slot = blockIdx.x, j = threadIdx.x;   // 128 thr
    const float* Wb = Wb_all + (size_t)r*128*128;
    const float* Wp = Wp_all + (size_t)r*64*64;
    float inv = 1.0f / (g_udeg[r*BB + slot] + EPSF);
    s_in[j] = g_uacc[((size_t)r*BB + slot)*128 + j] * inv;
    __syncthreads();
    if (j < 64) {
        s_mid[j] = s_in[j];
    } else {
        int m = j - 64;
        float a = 0.f;
        #pragma unroll 8
        for (int k = 0; k < 64; k++) a += s_in[64+k] * Wp[k*64 + m];
        s_mid[j] = a;
    }
    __syncthreads();
    float pr = 0.f;
    #pragma unroll 8
    for (int k = 0; k < 128; k++) pr += s_mid[k] * Wb[k*128 + j];
    s_pr[j] = pr;
    __syncthreads();
    float outv;
    if (j < 64) {
        outv = pr;
    } else {
        int k = j - 64;
        float a = 0.f;
        #pragma unroll 8
        for (int jj = 0; jj < 64; jj++) a += Wp[k*64 + jj] * s_pr[64+jj];
        outv = a;   // projB[k] = (Wp @ proj2)[k]
    }
    g_proj[((size_t)r*BB + slot)*128 + j] = outv;
}

// ---------------- u2 = user_feature @ W (weights/totals folded) ----------------
__global__ void k_userW(const float* __restrict__ Wm, const float* __restrict__ mgnn) {
    __shared__ float uf[64];
    int slot = blockIdx.x, j = threadIdx.x;
    float m0 = mgnn[0], m1 = mgnn[1], m2 = mgnn[2];
    float d0 = g_udeg[slot], d1 = g_udeg[BB+slot], d2 = g_udeg[2*BB+slot];
    float total = m0*d0 + m1*d1 + m2*d2;
    float c0 = m0*d0/(d0+EPSF), c1 = m1*d1/(d1+EPSF), c2 = m2*d2/(d2+EPSF);
    float v = c0*g_uacc[(size_t)slot*128 + j]
            + c1*g_uacc[((size_t)BB+slot)*128 + j]
            + c2*g_uacc[((size_t)2*BB+slot)*128 + j];
    uf[j] = v / (total + EPSF);
    __syncthreads();
    float acc = 0.f;
    #pragma unroll 8
    for (int k = 0; k < 64; k++) acc += uf[k] * Wm[k*64 + j];
    g_u2[slot*64 + j] = acc;
}

// ---------------- fused score1 + score2 + item L2 ----------------
__global__ void k_score(const int* __restrict__ user, const int* __restrict__ item,
                        const float* __restrict__ user_emb, const float* __restrict__ item_emb,
                        float* __restrict__ out) {
    int idx = blockIdx.x * blockDim.x + threadIdx.x;
    float n2 = 0.f;
    if (idx < BB*KK) {
        int b = idx / KK;
        int uid = user[b];
        int slot = g_map[uid];
        int it = item[idx];
        const float4* ue  = reinterpret_cast<const float4*>(user_emb) + (size_t)uid*16;
        const float4* u2  = reinterpret_cast<const float4*>(g_u2) + (size_t)slot*16;
        const float4* ie  = reinterpret_cast<const float4*>(item_emb) + (size_t)it*16;
        const float4* ifw = reinterpret_cast<const float4*>(g_item_featW) + (size_t)it*16;
        float s = 0.f;
        float4 ier[16];
        #pragma unroll
        for (int t = 0; t < 16; t++) {
            float4 a = ue[t], c = ie[t];
            ier[t] = c;
            s  += a.x*c.x + a.y*c.y + a.z*c.z + a.w*c.w;
            n2 += c.x*c.x + c.y*c.y + c.z*c.z + c.w*c.w;
        }
        #pragma unroll
        for (int t = 0; t < 16; t++) {
            float4 a = u2[t], c = ifw[t];
            s  += a.x*c.x + a.y*c.y + a.z*c.z + a.w*c.w;
            n2 += c.x*c.x + c.y*c.y + c.z*c.z + c.w*c.w;
        }
        float s2 = 0.f;
        #pragma unroll
        for (int r = 0; r < RREL; r++) {
            const float4* pr = reinterpret_cast<const float4*>(g_proj) + ((size_t)r*BB + slot)*32;
            const float4* ag = reinterpret_cast<const float4*>(g_item_agg + (size_t)r*IE) + (size_t)it*16;
            float dinv = 1.0f / (g_ig_deg[r*NITEMS + it] + EPSF);
            #pragma unroll
            for (int t = 0; t < 16; t++) {
                float4 a = pr[t], c = ier[t];
                s2 += a.x*c.x + a.y*c.y + a.z*c.z + a.w*c.w;
            }
            #pragma unroll
            for (int t = 0; t < 16; t++) {
                float4 a = pr[16+t], c = ag[t];
                s2 += dinv * (a.x*c.x + a.y*c.y + a.z*c.z + a.w*c.w);
            }
        }
        out[idx] = s + SCORE2_SCALE * s2;
    }
    __shared__ float red[256];
    red[threadIdx.x] = n2;
    __syncthreads();
    for (int s = 128; s > 0; s >>= 1) {
        if (threadIdx.x < s) red[threadIdx.x] += red[threadIdx.x + s];
        __syncthreads();
    }
    if (threadIdx.x == 0) atomicAdd(&g_l2i, (double)red[0]);
}

// ---------------- user-side L2 + final output element ----------------
__global__ void k_l2final(const int* __restrict__ user, const float* __restrict__ user_emb,
                          float* __restrict__ out, int out_n) {
    int b = threadIdx.x;   // 512
    int uid = user[b];
    int slot = g_map[uid];
    const float4* ue = reinterpret_cast<const float4*>(user_emb) + (size_t)uid*16;
    const float4* u2 = reinterpret_cast<const float4*>(g_u2) + (size_t)slot*16;
    float n2 = 0.f;
    #pragma unroll
    for (int t = 0; t < 16; t++) {
        float4 a = ue[t]; n2 += a.x*a.x + a.y*a.y + a.z*a.z + a.w*a.w;
        float4 c = u2[t]; n2 += c.x*c.x + c.y*c.y + c.z*c.z + c.w*c.w;
    }
    __shared__ float red[512];
    red[b] = n2;
    __syncthreads();
    for (int s = 256; s > 0; s >>= 1) {
        if (b < s) red[b] += red[b + s];
        __syncthreads();
    }
    if (b == 0 && out_n > BB*KK) {
        out[BB*KK] = (float)((double)L2C * ((double)KK * (double)red[0] + g_l2i));
    }
}

// ---------------- launch ----------------
extern "C" void kernel_launch(void* const* d_in, const int* in_sizes, int n_in,
                              void* d_out, int out_size) {
    const int*   user       = (const int*)  d_in[0];
    const int*   item       = (const int*)  d_in[1];
    const int*   rel_rows   = (const int*)  d_in[2];
    const int*   rel_cols   = (const int*)  d_in[3];
    const int*   ig_rows    = (const int*)  d_in[4];
    const int*   ig_cols    = (const int*)  d_in[5];
    const float* ig_vals    = (const float*)d_in[6];
    const int*   train_rows = (const int*)  d_in[7];
    const int*   train_cols = (const int*)  d_in[8];
    const float* user_emb   = (const float*)d_in[9];
    const float* item_emb   = (const float*)d_in[10];
    const float* mgnn       = (const float*)d_in[11];
    const float* Wb         = (const float*)d_in[12];
    const float* Wp         = (const float*)d_in[13];
    const float* Wm         = (const float*)d_in[14];
    float* out = (float*)d_out;

    k_zero<<<(RREL*IE/4 + 255)/256, 256>>>();
    k_map<<<(BB*KK + 255)/256, 256>>>(user, item);

    {   // prescan rel: 1M/4 threads per relation
        dim3 grid((NNZ_E/4 + 255)/256, RREL);
        k_prescan_rel<<<grid, 256>>>(rel_rows, rel_cols);
    }
    k_prescan_train<<<(NNZ_E/4 + 255)/256, 256>>>(train_cols);

    {   // ig scatter (filtered)
        dim3 grid((IG_NNZ_E/4*16 + 255)/256, RREL);
        k_ig<<<grid, 256>>>(ig_rows, ig_cols, ig_vals, item_emb);
    }
    // train scatter over compacted list (worst case NNZ_E entries)
    k_train<<<(NNZ_E/4*16 + 255)/256, 256>>>(train_rows, train_cols, user_emb);

    k_matmul_featW<<<512, 256>>>(Wm);

    {   // heavy rel accumulation
        dim3 grid(128, RREL);
        k_rel_heavy<<<grid, 256>>>(item_emb);
    }
    {
        dim3 grid(BB, RREL);
        k_proj<<<grid, 128>>>(Wb, Wp);
    }
    k_userW<<<BB, EMBED>>>(Wm, mgnn);

    k_score<<<(BB*KK + 255)/256, 256>>>(user, item, user_emb, item_emb, out);
    k_l2final<<<1, BB>>>(user, user_emb, out, out_size);
}

// round 4
// speedup vs baseline: 1.6514x; 1.0123x over previous
#include <cuda_runtime.h>
#include <cstdint>

#define NUSERS 100000
#define NITEMS 50000
#define EMBED 64
#define RREL 3
#define NNZ_E 1000000
#define IG_NNZ_E 500000
#define BB 512
#define KK 100
#define EPSF 1e-8f
#define SCORE2_SCALE (0.5f/3.0f)
#define L2C 1e-4f

#define IE (NITEMS*EMBED)        // 3,200,000 floats per relation plane
#define UBW 3200                 // user bitmap words (>= 100000/32)
#define IBW 1600                 // item bitmap words (>= 50000/32)

// ---------------- device scratch (static, allocation-free) ----------------
__device__ __align__(16) float g_item_agg[RREL*IE];
__device__ __align__(16) float g_item_feat[IE];
__device__ __align__(16) float g_item_featW[IE];
__device__ __align__(16) float g_ig_deg[RREL*NITEMS];
__device__ __align__(16) int   g_map[NUSERS];
__device__ __align__(16) unsigned g_ubit[UBW];   // batch-user bitmap
__device__ __align__(16) unsigned g_ibit[IBW];   // batch-item bitmap
__device__ __align__(16) unsigned g_nbit[IBW];   // "needed item_agg row" bitmap
__device__ __align__(16) float g_udeg[RREL*BB];
__device__ __align__(16) float g_uacc[RREL*BB*128];
__device__ __align__(16) float g_proj[RREL*BB*128];
__device__ __align__(16) float g_u2[BB*EMBED];
__device__ __align__(16) int2  g_crel[RREL*NNZ_E];    // compacted (slot,col)
__device__ __align__(16) int2  g_ctrain[NNZ_E];       // compacted (row,col)
__device__ int g_cnt_rel[RREL];
__device__ int g_cnt_train;
__device__ double g_l2i;

__device__ __forceinline__ void red_add_v4(float* addr, float4 v) {
    asm volatile("red.global.add.v4.f32 [%0], {%1,%2,%3,%4};"
                 :: "l"(addr), "f"(v.x), "f"(v.y), "f"(v.z), "f"(v.w) : "memory");
}

// ---------------- one-shot zero ----------------
__global__ void k_zero() {
    int idx = blockIdx.x * blockDim.x + threadIdx.x;
    float4 z4 = make_float4(0.f,0.f,0.f,0.f);
    if (idx < RREL*IE/4)       reinterpret_cast<float4*>(g_item_agg)[idx] = z4;
    if (idx < IE/4)            reinterpret_cast<float4*>(g_item_feat)[idx] = z4;
    if (idx < RREL*NITEMS/4)   reinterpret_cast<float4*>(g_ig_deg)[idx] = z4;
    if (idx < RREL*BB*128/4)   reinterpret_cast<float4*>(g_uacc)[idx] = z4;
    if (idx < RREL*BB)         g_udeg[idx] = 0.f;
    if (idx < NUSERS/4)        reinterpret_cast<int4*>(g_map)[idx] = make_int4(-1,-1,-1,-1);
    if (idx < UBW)             g_ubit[idx] = 0u;
    if (idx < IBW)             { g_ibit[idx] = 0u; g_nbit[idx] = 0u; }
    if (idx < RREL)            g_cnt_rel[idx] = 0;
    if (idx == 0)              { g_cnt_train = 0; g_l2i = 0.0; }
}

// ---------------- build maps / bitmaps ----------------
__global__ void k_map(const int* __restrict__ user, const int* __restrict__ item) {
    int idx = blockIdx.x * blockDim.x + threadIdx.x;   // covers BB*KK
    if (idx < BB) {
        int uid = user[idx];
        g_map[uid] = idx;                       // dup uids: any winner, data identical
        atomicOr(&g_ubit[uid >> 5], 1u << (uid & 31));
    }
    if (idx < BB*KK) {
        int it = item[idx];
        atomicOr(&g_ibit[it >> 5], 1u << (it & 31));
        atomicOr(&g_nbit[it >> 5], 1u << (it & 31));
    }
}

// ---------------- prescan rel edges: warp-aggregated compaction ----------------
__global__ void k_prescan_rel(const int* __restrict__ rows_all, const int* __restrict__ cols_all) {
    int r = blockIdx.y;
    const int* rows = rows_all + (size_t)r*NNZ_E;
    const int* cols = cols_all + (size_t)r*NNZ_E;
    int g = blockIdx.x * blockDim.x + threadIdx.x;
    int lane = threadIdx.x & 31;
    bool inrange = (g < NNZ_E/4);
    int e0 = g * 4;
    int4 rr = inrange ? *reinterpret_cast<const int4*>(rows + e0) : make_int4(0,0,0,0);
    #pragma unroll
    for (int q = 0; q < 4; q++) {
        int row = (q==0)?rr.x:(q==1)?rr.y:(q==2)?rr.z:rr.w;
        bool pass = false;
        if (inrange) {
            unsigned w = __ldg(&g_ubit[row >> 5]);
            pass = (w >> (row & 31)) & 1u;
        }
        unsigned m = __ballot_sync(0xffffffffu, pass);
        if (m == 0) continue;
        int cnt = __popc(m);
        int leader = __ffs(m) - 1;
        int base = 0;
        if (lane == leader) base = atomicAdd(&g_cnt_rel[r], cnt);
        base = __shfl_sync(0xffffffffu, base, leader);
        if (pass) {
            int rank = __popc(m & ((1u << lane) - 1u));
            int slot = g_map[row];
            int col = __ldg(&cols[e0 + q]);
            g_crel[(size_t)r*NNZ_E + base + rank] = make_int2(slot, col);
            atomicAdd(&g_udeg[r*BB + slot], 1.0f);
            atomicOr(&g_nbit[col >> 5], 1u << (col & 31));
        }
    }
}

// ---------------- prescan train edges: warp-aggregated, stores (row,col) -----
__global__ void k_prescan_train(const int* __restrict__ rows, const int* __restrict__ cols) {
    int g = blockIdx.x * blockDim.x + threadIdx.x;
    int lane = threadIdx.x & 31;
    bool inrange = (g < NNZ_E/4);
    int e0 = g * 4;
    int4 cc = inrange ? *reinterpret_cast<const int4*>(cols + e0) : make_int4(0,0,0,0);
    #pragma unroll
    for (int q = 0; q < 4; q++) {
        int col = (q==0)?cc.x:(q==1)?cc.y:(q==2)?cc.z:cc.w;
        bool pass = false;
        if (inrange) {
            unsigned w = __ldg(&g_ibit[col >> 5]);
            pass = (w >> (col & 31)) & 1u;
        }
        unsigned m = __ballot_sync(0xffffffffu, pass);
        if (m == 0) continue;
        int cnt = __popc(m);
        int leader = __ffs(m) - 1;
        int base = 0;
        if (lane == leader) base = atomicAdd(&g_cnt_train, cnt);
        base = __shfl_sync(0xffffffffu, base, leader);
        if (pass) {
            int rank = __popc(m & ((1u << lane) - 1u));
            int row = __ldg(&rows[e0 + q]);
            g_ctrain[base + rank] = make_int2(row, col);
        }
    }
}

// ---------------- item-graph scatter (needed-rows only), 4 edges / thread ----
__global__ void k_ig(const int* __restrict__ rows_all, const int* __restrict__ cols_all,
                     const float* __restrict__ vals_all, const float* __restrict__ item_emb) {
    int r = blockIdx.y;
    const int*   rows = rows_all + (size_t)r*IG_NNZ_E;
    const int*   cols = cols_all + (size_t)r*IG_NNZ_E;
    const float* vals = vals_all + (size_t)r*IG_NNZ_E;
    float* agg = g_item_agg + (size_t)r*IE;
    float* deg = g_ig_deg + (size_t)r*NITEMS;

    int t = blockIdx.x * blockDim.x + threadIdx.x;
    int g = t >> 4;
    if (g >= IG_NNZ_E/4) return;
    int p = t & 15;
    int e0 = g * 4;
    int4  rr = *reinterpret_cast<const int4*>(rows + e0);
    int4   c = *reinterpret_cast<const int4*>(cols + e0);
    float4 v = *reinterpret_cast<const float4*>(vals + e0);
    const float4* E = reinterpret_cast<const float4*>(item_emb);
    bool n0 = (__ldg(&g_nbit[rr.x >> 5]) >> (rr.x & 31)) & 1u;
    bool n1 = (__ldg(&g_nbit[rr.y >> 5]) >> (rr.y & 31)) & 1u;
    bool n2 = (__ldg(&g_nbit[rr.z >> 5]) >> (rr.z & 31)) & 1u;
    bool n3 = (__ldg(&g_nbit[rr.w >> 5]) >> (rr.w & 31)) & 1u;
    if (n0) { float4 x = E[(size_t)c.x*16 + p]; x.x*=v.x; x.y*=v.x; x.z*=v.x; x.w*=v.x;
              red_add_v4(agg + (size_t)rr.x*64 + p*4, x); }
    if (n1) { float4 x = E[(size_t)c.y*16 + p]; x.x*=v.y; x.y*=v.y; x.z*=v.y; x.w*=v.y;
              red_add_v4(agg + (size_t)rr.y*64 + p*4, x); }
    if (n2) { float4 x = E[(size_t)c.z*16 + p]; x.x*=v.z; x.y*=v.z; x.z*=v.z; x.w*=v.z;
              red_add_v4(agg + (size_t)rr.z*64 + p*4, x); }
    if (n3) { float4 x = E[(size_t)c.w*16 + p]; x.x*=v.w; x.y*=v.w; x.z*=v.w; x.w*=v.w;
              red_add_v4(agg + (size_t)rr.w*64 + p*4, x); }
    if (p == 0) {
        if (n0) atomicAdd(deg + rr.x, v.x);
        if (n1) atomicAdd(deg + rr.y, v.y);
        if (n2) atomicAdd(deg + rr.z, v.z);
        if (n3) atomicAdd(deg + rr.w, v.w);
    }
}

// ---------------- train scatter over compacted (row,col) list ----------------
__global__ void k_train(const float* __restrict__ user_emb) {
    int t = blockIdx.x * blockDim.x + threadIdx.x;
    int g = t >> 4;
    int p = t & 15;
    int n = g_cnt_train;
    int base = g * 4;
    if (base >= n) return;
    const int* lst = reinterpret_cast<const int*>(g_ctrain);
    int4 a = *reinterpret_cast<const int4*>(lst + base*2);       // (r0,c0,r1,c1)
    int4 b = *reinterpret_cast<const int4*>(lst + base*2 + 4);   // (r2,c2,r3,c3)
    const float4* E = reinterpret_cast<const float4*>(user_emb);
    int rows[4] = {a.x, a.z, b.x, b.z};
    int colz[4] = {a.y, a.w, b.y, b.w};
    #pragma unroll
    for (int q = 0; q < 4; q++) {
        if (base + q >= n) break;
        float4 x = E[(size_t)rows[q]*16 + p];
        red_add_v4(g_item_feat + (size_t)colz[q]*64 + p*4, x);
    }
}

// ---------------- (NITEMS x 64) @ (64 x 64) ----------------
__global__ void k_matmul_featW(const float* __restrict__ Wm) {
    __shared__ float4 w_s[64*16];
    __shared__ float4 a_s[16*16];
    int tid = threadIdx.x;          // 256
    const float4* W4 = reinterpret_cast<const float4*>(Wm);
    for (int t = tid; t < 64*16; t += 256) w_s[t] = W4[t];
    __syncthreads();
    int r = tid >> 4, j = tid & 15;
    for (int chunk = blockIdx.x; chunk < NITEMS/16; chunk += gridDim.x) {
        int row0 = chunk * 16;
        a_s[r*16 + j] = reinterpret_cast<const float4*>(g_item_feat)[(row0 + r)*16 + j];
        __syncthreads();
        float4 acc = make_float4(0.f,0.f,0.f,0.f);
        #pragma unroll
        for (int kk = 0; kk < 16; kk++) {
            float4 a  = a_s[r*16 + kk];
            float4 w0 = w_s[(4*kk+0)*16 + j];
            float4 w1 = w_s[(4*kk+1)*16 + j];
            float4 w2 = w_s[(4*kk+2)*16 + j];
            float4 w3 = w_s[(4*kk+3)*16 + j];
            acc.x += a.x*w0.x + a.y*w1.x + a.z*w2.x + a.w*w3.x;
            acc.y += a.x*w0.y + a.y*w1.y + a.z*w2.y + a.w*w3.y;
            acc.z += a.x*w0.z + a.y*w1.z + a.z*w2.z + a.w*w3.z;
            acc.w += a.x*w0.w + a.y*w1.w + a.z*w2.w + a.w*w3.w;
        }
        reinterpret_cast<float4*>(g_item_featW)[(row0 + r)*16 + j] = acc;
        __syncthreads();
    }
}

// ---------------- heavy rel accumulation over compacted entries ----------------
__global__ void k_rel_heavy(const float* __restrict__ item_emb) {
    int r = blockIdx.y;
    int ne = g_cnt_rel[r];
    const int2* lst = g_crel + (size_t)r*NNZ_E;
    const float4* agg4 = reinterpret_cast<const float4*>(g_item_agg + (size_t)r*IE);
    const float* deg = g_ig_deg + (size_t)r*NITEMS;
    int p = threadIdx.x & 15;
    int lane_entry = (blockIdx.x * blockDim.x + threadIdx.x) >> 4;
    int stride = (gridDim.x * blockDim.x) >> 4;
    for (int idx = lane_entry; idx < ne; idx += stride) {
        int2 ent = lst[idx];
        int slot = ent.x, col = ent.y;
        float4 ie = reinterpret_cast<const float4*>(item_emb)[(size_t)col*16 + p];
        float4 ag = agg4[(size_t)col*16 + p];
        float inv = 1.0f / (__ldg(&deg[col]) + EPSF);
        ag.x *= inv; ag.y *= inv; ag.z *= inv; ag.w *= inv;
        float* dst = g_uacc + ((size_t)r*BB + slot)*128;
        red_add_v4(dst + p*4, ie);
        red_add_v4(dst + 64 + p*4, ag);
    }
}

// ---------------- proj with Wp folding; outputs [proj1 | Wp@proj2] ----------------
__global__ void k_proj(const float* __restrict__ Wb_all, const float* __restrict__ Wp_all) {
    __shared__ float s_in[128], s_mid[128], s_pr[128];
    int r = blockIdx.y, slot = blockIdx.x, j = threadIdx.x;   // 128 thr
    const float* Wb = Wb_all + (size_t)r*128*128;
    const float* Wp = Wp_all + (size_t)r*64*64;
    float inv = 1.0f / (g_udeg[r*BB + slot] + EPSF);
    s_in[j] = g_uacc[((size_t)r*BB + slot)*128 + j] * inv;
    __syncthreads();
    if (j < 64) {
        s_mid[j] = s_in[j];
    } else {
        int m = j - 64;
        float a = 0.f;
        #pragma unroll 8
        for (int k = 0; k < 64; k++) a += s_in[64+k] * Wp[k*64 + m];
        s_mid[j] = a;
    }
    __syncthreads();
    float pr = 0.f;
    #pragma unroll 8
    for (int k = 0; k < 128; k++) pr += s_mid[k] * Wb[k*128 + j];
    s_pr[j] = pr;
    __syncthreads();
    float outv;
    if (j < 64) {
        outv = pr;
    } else {
        int k = j - 64;
        float a = 0.f;
        #pragma unroll 8
        for (int jj = 0; jj < 64; jj++) a += Wp[k*64 + jj] * s_pr[64+jj];
        outv = a;   // projB[k] = (Wp @ proj2)[k]
    }
    g_proj[((size_t)r*BB + slot)*128 + j] = outv;
}

// ---------------- u2 = user_feature @ W (weights/totals folded) ----------------
__global__ void k_userW(const float* __restrict__ Wm, const float* __restrict__ mgnn) {
    __shared__ float uf[64];
    int slot = blockIdx.x, j = threadIdx.x;
    float m0 = mgnn[0], m1 = mgnn[1], m2 = mgnn[2];
    float d0 = g_udeg[slot], d1 = g_udeg[BB+slot], d2 = g_udeg[2*BB+slot];
    float total = m0*d0 + m1*d1 + m2*d2;
    float c0 = m0*d0/(d0+EPSF), c1 = m1*d1/(d1+EPSF), c2 = m2*d2/(d2+EPSF);
    float v = c0*g_uacc[(size_t)slot*128 + j]
            + c1*g_uacc[((size_t)BB+slot)*128 + j]
            + c2*g_uacc[((size_t)2*BB+slot)*128 + j];
    uf[j] = v / (total + EPSF);
    __syncthreads();
    float acc = 0.f;
    #pragma unroll 8
    for (int k = 0; k < 64; k++) acc += uf[k] * Wm[k*64 + j];
    g_u2[slot*64 + j] = acc;
}

// ---------------- fused score1 + score2 + item L2 ----------------
__global__ void k_score(const int* __restrict__ user, const int* __restrict__ item,
                        const float* __restrict__ user_emb, const float* __restrict__ item_emb,
                        float* __restrict__ out) {
    int idx = blockIdx.x * blockDim.x + threadIdx.x;
    float n2 = 0.f;
    if (idx < BB*KK) {
        int b = idx / KK;
        int uid = user[b];
        int slot = g_map[uid];
        int it = item[idx];
        const float4* ue  = reinterpret_cast<const float4*>(user_emb) + (size_t)uid*16;
        const float4* u2  = reinterpret_cast<const float4*>(g_u2) + (size_t)slot*16;
        const float4* ie  = reinterpret_cast<const float4*>(item_emb) + (size_t)it*16;
        const float4* ifw = reinterpret_cast<const float4*>(g_item_featW) + (size_t)it*16;
        float s = 0.f;
        float4 ier[16];
        #pragma unroll
        for (int t = 0; t < 16; t++) {
            float4 a = ue[t], c = ie[t];
            ier[t] = c;
            s  += a.x*c.x + a.y*c.y + a.z*c.z + a.w*c.w;
            n2 += c.x*c.x + c.y*c.y + c.z*c.z + c.w*c.w;
        }
        #pragma unroll
        for (int t = 0; t < 16; t++) {
            float4 a = u2[t], c = ifw[t];
            s  += a.x*c.x + a.y*c.y + a.z*c.z + a.w*c.w;
            n2 += c.x*c.x + c.y*c.y + c.z*c.z + c.w*c.w;
        }
        float s2 = 0.f;
        #pragma unroll
        for (int r = 0; r < RREL; r++) {
            const float4* pr = reinterpret_cast<const float4*>(g_proj) + ((size_t)r*BB + slot)*32;
            const float4* ag = reinterpret_cast<const float4*>(g_item_agg + (size_t)r*IE) + (size_t)it*16;
            float dinv = 1.0f / (g_ig_deg[r*NITEMS + it] + EPSF);
            #pragma unroll
            for (int t = 0; t < 16; t++) {
                float4 a = pr[t], c = ier[t];
                s2 += a.x*c.x + a.y*c.y + a.z*c.z + a.w*c.w;
            }
            #pragma unroll
            for (int t = 0; t < 16; t++) {
                float4 a = pr[16+t], c = ag[t];
                s2 += dinv * (a.x*c.x + a.y*c.y + a.z*c.z + a.w*c.w);
            }
        }
        out[idx] = s + SCORE2_SCALE * s2;
    }
    __shared__ float red[256];
    red[threadIdx.x] = n2;
    __syncthreads();
    for (int s = 128; s > 0; s >>= 1) {
        if (threadIdx.x < s) red[threadIdx.x] += red[threadIdx.x + s];
        __syncthreads();
    }
    if (threadIdx.x == 0) atomicAdd(&g_l2i, (double)red[0]);
}

// ---------------- user-side L2 + final output element ----------------
__global__ void k_l2final(const int* __restrict__ user, const float* __restrict__ user_emb,
                          float* __restrict__ out, int out_n) {
    int b = threadIdx.x;   // 512
    int uid = user[b];
    int slot = g_map[uid];
    const float4* ue = reinterpret_cast<const float4*>(user_emb) + (size_t)uid*16;
    const float4* u2 = reinterpret_cast<const float4*>(g_u2) + (size_t)slot*16;
    float n2 = 0.f;
    #pragma unroll
    for (int t = 0; t < 16; t++) {
        float4 a = ue[t]; n2 += a.x*a.x + a.y*a.y + a.z*a.z + a.w*a.w;
        float4 c = u2[t]; n2 += c.x*c.x + c.y*c.y + c.z*c.z + c.w*c.w;
    }
    __shared__ float red[512];
    red[b] = n2;
    __syncthreads();
    for (int s = 256; s > 0; s >>= 1) {
        if (b < s) red[b] += red[b + s];
        __syncthreads();
    }
    if (b == 0 && out_n > BB*KK) {
        out[BB*KK] = (float)((double)L2C * ((double)KK * (double)red[0] + g_l2i));
    }
}

// ---------------- launch ----------------
extern "C" void kernel_launch(void* const* d_in, const int* in_sizes, int n_in,
                              void* d_out, int out_size) {
    const int*   user       = (const int*)  d_in[0];
    const int*   item       = (const int*)  d_in[1];
    const int*   rel_rows   = (const int*)  d_in[2];
    const int*   rel_cols   = (const int*)  d_in[3];
    const int*   ig_rows    = (const int*)  d_in[4];
    const int*   ig_cols    = (const int*)  d_in[5];
    const float* ig_vals    = (const float*)d_in[6];
    const int*   train_rows = (const int*)  d_in[7];
    const int*   train_cols = (const int*)  d_in[8];
    const float* user_emb   = (const float*)d_in[9];
    const float* item_emb   = (const float*)d_in[10];
    const float* mgnn       = (const float*)d_in[11];
    const float* Wb         = (const float*)d_in[12];
    const float* Wp         = (const float*)d_in[13];
    const float* Wm         = (const float*)d_in[14];
    float* out = (float*)d_out;

    k_zero<<<(RREL*IE/4 + 255)/256, 256>>>();
    k_map<<<(BB*KK + 255)/256, 256>>>(user, item);

    {
        dim3 grid((NNZ_E/4 + 255)/256, RREL);
        k_prescan_rel<<<grid, 256>>>(rel_rows, rel_cols);
    }
    k_prescan_train<<<(NNZ_E/4 + 255)/256, 256>>>(train_rows, train_cols);

    {
        dim3 grid((IG_NNZ_E/4*16 + 255)/256, RREL);
        k_ig<<<grid, 256>>>(ig_rows, ig_cols, ig_vals, item_emb);
    }
    k_train<<<(NNZ_E/4*16 + 255)/256, 256>>>(user_emb);

    k_matmul_featW<<<512, 256>>>(Wm);

    {
        dim3 grid(128, RREL);
        k_rel_heavy<<<grid, 256>>>(item_emb);
    }
    {
        dim3 grid(BB, RREL);
        k_proj<<<grid, 128>>>(Wb, Wp);
    }
    k_userW<<<BB, EMBED>>>(Wm, mgnn);

    k_score<<<(BB*KK + 255)/256, 256>>>(user, item, user_emb, item_emb, out);
    k_l2final<<<1, BB>>>(user, user_emb, out, out_size);
}

// round 5
// speedup vs baseline: 1.7820x; 1.0791x over previous
#include <cuda_runtime.h>
#include <cstdint>

#define NUSERS 100000
#define NITEMS 50000
#define EMBED 64
#define RREL 3
#define NNZ_E 1000000
#define IG_NNZ_E 500000
#define BB 512
#define KK 100
#define EPSF 1e-8f
#define SCORE2_SCALE (0.5f/3.0f)
#define L2C 1e-4f

#define IE (NITEMS*EMBED)        // 3,200,000 floats per relation plane
#define UBW 3200                 // user bitmap words (>= 100000/32)
#define IBW 1600                 // item bitmap words (>= 50000/32)

// ---------------- device scratch (static, allocation-free) ----------------
__device__ __align__(16) float g_item_agg[RREL*IE];
__device__ __align__(16) float g_item_feat[IE];
__device__ __align__(16) float g_item_featW[IE];
__device__ __align__(16) float g_ig_deg[RREL*NITEMS];
__device__ __align__(16) int   g_map[NUSERS];
__device__ __align__(16) unsigned g_ubit[UBW];   // batch-user bitmap
__device__ __align__(16) unsigned g_ibit[IBW];   // batch-item bitmap
__device__ __align__(16) unsigned g_nbit[IBW];   // "needed item_agg row" bitmap
__device__ __align__(16) float g_udeg[RREL*BB];
__device__ __align__(16) float g_uacc[RREL*BB*128];
__device__ __align__(16) float g_proj[RREL*BB*128];
__device__ __align__(16) float g_u2[BB*EMBED];
__device__ __align__(16) int2  g_crel[RREL*NNZ_E];    // compacted (slot,col)
__device__ int g_cnt_rel[RREL];
__device__ double g_l2i;

__device__ __forceinline__ void red_add_v4(float* addr, float4 v) {
    asm volatile("red.global.add.v4.f32 [%0], {%1,%2,%3,%4};"
                 :: "l"(addr), "f"(v.x), "f"(v.y), "f"(v.z), "f"(v.w) : "memory");
}

// ---------------- one-shot zero ----------------
__global__ void k_zero() {
    int idx = blockIdx.x * blockDim.x + threadIdx.x;
    float4 z4 = make_float4(0.f,0.f,0.f,0.f);
    if (idx < RREL*IE/4)       reinterpret_cast<float4*>(g_item_agg)[idx] = z4;
    if (idx < IE/4)            reinterpret_cast<float4*>(g_item_feat)[idx] = z4;
    if (idx < RREL*NITEMS/4)   reinterpret_cast<float4*>(g_ig_deg)[idx] = z4;
    if (idx < RREL*BB*128/4)   reinterpret_cast<float4*>(g_uacc)[idx] = z4;
    if (idx < RREL*BB)         g_udeg[idx] = 0.f;
    if (idx < NUSERS/4)        reinterpret_cast<int4*>(g_map)[idx] = make_int4(-1,-1,-1,-1);
    if (idx < UBW)             g_ubit[idx] = 0u;
    if (idx < IBW)             { g_ibit[idx] = 0u; g_nbit[idx] = 0u; }
    if (idx < RREL)            g_cnt_rel[idx] = 0;
    if (idx == 0)              g_l2i = 0.0;
}

// ---------------- build maps / bitmaps ----------------
__global__ void k_map(const int* __restrict__ user, const int* __restrict__ item) {
    int idx = blockIdx.x * blockDim.x + threadIdx.x;   // covers BB*KK
    if (idx < BB) {
        int uid = user[idx];
        g_map[uid] = idx;                       // dup uids: any winner, data identical
        atomicOr(&g_ubit[uid >> 5], 1u << (uid & 31));
    }
    if (idx < BB*KK) {
        int it = item[idx];
        atomicOr(&g_ibit[it >> 5], 1u << (it & 31));
        atomicOr(&g_nbit[it >> 5], 1u << (it & 31));
    }
}

// ---------------- prescan rel edges: warp-aggregated compaction ----------------
__global__ void k_prescan_rel(const int* __restrict__ rows_all, const int* __restrict__ cols_all) {
    int r = blockIdx.y;
    const int* rows = rows_all + (size_t)r*NNZ_E;
    const int* cols = cols_all + (size_t)r*NNZ_E;
    int g = blockIdx.x * blockDim.x + threadIdx.x;
    int lane = threadIdx.x & 31;
    bool inrange = (g < NNZ_E/4);
    int e0 = g * 4;
    int4 rr = inrange ? *reinterpret_cast<const int4*>(rows + e0) : make_int4(0,0,0,0);
    #pragma unroll
    for (int q = 0; q < 4; q++) {
        int row = (q==0)?rr.x:(q==1)?rr.y:(q==2)?rr.z:rr.w;
        bool pass = false;
        if (inrange) {
            unsigned w = __ldg(&g_ubit[row >> 5]);
            pass = (w >> (row & 31)) & 1u;
        }
        unsigned m = __ballot_sync(0xffffffffu, pass);
        if (m == 0) continue;
        int cnt = __popc(m);
        int leader = __ffs(m) - 1;
        int base = 0;
        if (lane == leader) base = atomicAdd(&g_cnt_rel[r], cnt);
        base = __shfl_sync(0xffffffffu, base, leader);
        if (pass) {
            int rank = __popc(m & ((1u << lane) - 1u));
            int slot = g_map[row];
            int col = __ldg(&cols[e0 + q]);
            g_crel[(size_t)r*NNZ_E + base + rank] = make_int2(slot, col);
            atomicAdd(&g_udeg[r*BB + slot], 1.0f);
            atomicOr(&g_nbit[col >> 5], 1u << (col & 31));
        }
    }
}

// ---------------- item-graph scatter (needed-rows only), 4 edges / thread ----
__global__ void k_ig(const int* __restrict__ rows_all, const int* __restrict__ cols_all,
                     const float* __restrict__ vals_all, const float* __restrict__ item_emb) {
    int r = blockIdx.y;
    const int*   rows = rows_all + (size_t)r*IG_NNZ_E;
    const int*   cols = cols_all + (size_t)r*IG_NNZ_E;
    const float* vals = vals_all + (size_t)r*IG_NNZ_E;
    float* agg = g_item_agg + (size_t)r*IE;
    float* deg = g_ig_deg + (size_t)r*NITEMS;

    int t = blockIdx.x * blockDim.x + threadIdx.x;
    int g = t >> 4;
    if (g >= IG_NNZ_E/4) return;
    int p = t & 15;
    int e0 = g * 4;
    int4  rr = *reinterpret_cast<const int4*>(rows + e0);
    int4   c = *reinterpret_cast<const int4*>(cols + e0);
    float4 v = *reinterpret_cast<const float4*>(vals + e0);
    const float4* E = reinterpret_cast<const float4*>(item_emb);
    bool n0 = (__ldg(&g_nbit[rr.x >> 5]) >> (rr.x & 31)) & 1u;
    bool n1 = (__ldg(&g_nbit[rr.y >> 5]) >> (rr.y & 31)) & 1u;
    bool n2 = (__ldg(&g_nbit[rr.z >> 5]) >> (rr.z & 31)) & 1u;
    bool n3 = (__ldg(&g_nbit[rr.w >> 5]) >> (rr.w & 31)) & 1u;
    if (n0) { float4 x = E[(size_t)c.x*16 + p]; x.x*=v.x; x.y*=v.x; x.z*=v.x; x.w*=v.x;
              red_add_v4(agg + (size_t)rr.x*64 + p*4, x); }
    if (n1) { float4 x = E[(size_t)c.y*16 + p]; x.x*=v.y; x.y*=v.y; x.z*=v.y; x.w*=v.y;
              red_add_v4(agg + (size_t)rr.y*64 + p*4, x); }
    if (n2) { float4 x = E[(size_t)c.z*16 + p]; x.x*=v.z; x.y*=v.z; x.z*=v.z; x.w*=v.z;
              red_add_v4(agg + (size_t)rr.z*64 + p*4, x); }
    if (n3) { float4 x = E[(size_t)c.w*16 + p]; x.x*=v.w; x.y*=v.w; x.z*=v.w; x.w*=v.w;
              red_add_v4(agg + (size_t)rr.w*64 + p*4, x); }
    if (p == 0) {
        if (n0) atomicAdd(deg + rr.x, v.x);
        if (n1) atomicAdd(deg + rr.y, v.y);
        if (n2) atomicAdd(deg + rr.z, v.z);
        if (n3) atomicAdd(deg + rr.w, v.w);
    }
}

// ---------------- fused train filter + scatter, 4 edges / 16-thread group ----
__global__ void k_train_fused(const int* __restrict__ rows, const int* __restrict__ cols,
                              const float* __restrict__ user_emb) {
    int t = blockIdx.x * blockDim.x + threadIdx.x;
    int g = t >> 4;
    if (g >= NNZ_E/4) return;
    int p = t & 15;
    int e0 = g * 4;
    int4 cc = *reinterpret_cast<const int4*>(cols + e0);
    int4 rr = *reinterpret_cast<const int4*>(rows + e0);
    const float4* E = reinterpret_cast<const float4*>(user_emb);
    bool b0 = (__ldg(&g_ibit[cc.x >> 5]) >> (cc.x & 31)) & 1u;
    bool b1 = (__ldg(&g_ibit[cc.y >> 5]) >> (cc.y & 31)) & 1u;
    bool b2 = (__ldg(&g_ibit[cc.z >> 5]) >> (cc.z & 31)) & 1u;
    bool b3 = (__ldg(&g_ibit[cc.w >> 5]) >> (cc.w & 31)) & 1u;
    if (b0) { float4 x = E[(size_t)rr.x*16 + p]; red_add_v4(g_item_feat + (size_t)cc.x*64 + p*4, x); }
    if (b1) { float4 x = E[(size_t)rr.y*16 + p]; red_add_v4(g_item_feat + (size_t)cc.y*64 + p*4, x); }
    if (b2) { float4 x = E[(size_t)rr.z*16 + p]; red_add_v4(g_item_feat + (size_t)cc.z*64 + p*4, x); }
    if (b3) { float4 x = E[(size_t)rr.w*16 + p]; red_add_v4(g_item_feat + (size_t)cc.w*64 + p*4, x); }
}

// ---------------- (NITEMS x 64) @ (64 x 64), batch-item rows only ----------------
__global__ void k_matmul_featW(const float* __restrict__ Wm) {
    __shared__ float4 w_s[64*16];
    __shared__ float4 a_s[16*16];
    int tid = threadIdx.x;          // 256
    const float4* W4 = reinterpret_cast<const float4*>(Wm);
    for (int t = tid; t < 64*16; t += 256) w_s[t] = W4[t];
    __syncthreads();
    int r = tid >> 4, j = tid & 15;
    for (int chunk = blockIdx.x; chunk < NITEMS/16; chunk += gridDim.x) {
        int row0 = chunk * 16;
        // 16 consecutive rows -> 16 bits within one bitmap word
        unsigned wbits = (g_ibit[row0 >> 5] >> (row0 & 31)) & 0xFFFFu;
        if (wbits == 0u) continue;   // nobody reads these rows
        a_s[r*16 + j] = reinterpret_cast<const float4*>(g_item_feat)[(row0 + r)*16 + j];
        __syncthreads();
        float4 acc = make_float4(0.f,0.f,0.f,0.f);
        #pragma unroll
        for (int kk = 0; kk < 16; kk++) {
            float4 a  = a_s[r*16 + kk];
            float4 w0 = w_s[(4*kk+0)*16 + j];
            float4 w1 = w_s[(4*kk+1)*16 + j];
            float4 w2 = w_s[(4*kk+2)*16 + j];
            float4 w3 = w_s[(4*kk+3)*16 + j];
            acc.x += a.x*w0.x + a.y*w1.x + a.z*w2.x + a.w*w3.x;
            acc.y += a.x*w0.y + a.y*w1.y + a.z*w2.y + a.w*w3.y;
            acc.z += a.x*w0.z + a.y*w1.z + a.z*w2.z + a.w*w3.z;
            acc.w += a.x*w0.w + a.y*w1.w + a.z*w2.w + a.w*w3.w;
        }
        if ((wbits >> r) & 1u)
            reinterpret_cast<float4*>(g_item_featW)[(row0 + r)*16 + j] = acc;
        __syncthreads();
    }
}

// ---------------- heavy rel accumulation over compacted entries ----------------
__global__ void k_rel_heavy(const float* __restrict__ item_emb) {
    int r = blockIdx.y;
    int ne = g_cnt_rel[r];
    const int2* lst = g_crel + (size_t)r*NNZ_E;
    const float4* agg4 = reinterpret_cast<const float4*>(g_item_agg + (size_t)r*IE);
    const float* deg = g_ig_deg + (size_t)r*NITEMS;
    int p = threadIdx.x & 15;
    int lane_entry = (blockIdx.x * blockDim.x + threadIdx.x) >> 4;
    int stride = (gridDim.x * blockDim.x) >> 4;
    for (int idx = lane_entry; idx < ne; idx += stride) {
        int2 ent = lst[idx];
        int slot = ent.x, col = ent.y;
        float4 ie = reinterpret_cast<const float4*>(item_emb)[(size_t)col*16 + p];
        float4 ag = agg4[(size_t)col*16 + p];
        float inv = 1.0f / (__ldg(&deg[col]) + EPSF);
        ag.x *= inv; ag.y *= inv; ag.z *= inv; ag.w *= inv;
        float* dst = g_uacc + ((size_t)r*BB + slot)*128;
        red_add_v4(dst + p*4, ie);
        red_add_v4(dst + 64 + p*4, ag);
    }
}

// ---------------- proj with Wp folding; outputs [proj1 | Wp@proj2] ----------------
__global__ void k_proj(const float* __restrict__ Wb_all, const float* __restrict__ Wp_all) {
    __shared__ float s_in[128], s_mid[128], s_pr[128];
    int r = blockIdx.y, slot = blockIdx.x, j = threadIdx.x;   // 128 thr
    const float* Wb = Wb_all + (size_t)r*128*128;
    const float* Wp = Wp_all + (size_t)r*64*64;
    float inv = 1.0f / (g_udeg[r*BB + slot] + EPSF);
    s_in[j] = g_uacc[((size_t)r*BB + slot)*128 + j] * inv;
    __syncthreads();
    if (j < 64) {
        s_mid[j] = s_in[j];
    } else {
        int m = j - 64;
        float a = 0.f;
        #pragma unroll 8
        for (int k = 0; k < 64; k++) a += s_in[64+k] * Wp[k*64 + m];
        s_mid[j] = a;
    }
    __syncthreads();
    float pr = 0.f;
    #pragma unroll 8
    for (int k = 0; k < 128; k++) pr += s_mid[k] * Wb[k*128 + j];
    s_pr[j] = pr;
    __syncthreads();
    float outv;
    if (j < 64) {
        outv = pr;
    } else {
        int k = j - 64;
        float a = 0.f;
        #pragma unroll 8
        for (int jj = 0; jj < 64; jj++) a += Wp[k*64 + jj] * s_pr[64+jj];
        outv = a;   // projB[k] = (Wp @ proj2)[k]
    }
    g_proj[((size_t)r*BB + slot)*128 + j] = outv;
}

// ---------------- u2 = user_feature @ W (weights/totals folded) ----------------
__global__ void k_userW(const float* __restrict__ Wm, const float* __restrict__ mgnn) {
    __shared__ float uf[64];
    int slot = blockIdx.x, j = threadIdx.x;
    float m0 = mgnn[0], m1 = mgnn[1], m2 = mgnn[2];
    float d0 = g_udeg[slot], d1 = g_udeg[BB+slot], d2 = g_udeg[2*BB+slot];
    float total = m0*d0 + m1*d1 + m2*d2;
    float c0 = m0*d0/(d0+EPSF), c1 = m1*d1/(d1+EPSF), c2 = m2*d2/(d2+EPSF);
    float v = c0*g_uacc[(size_t)slot*128 + j]
            + c1*g_uacc[((size_t)BB+slot)*128 + j]
            + c2*g_uacc[((size_t)2*BB+slot)*128 + j];
    uf[j] = v / (total + EPSF);
    __syncthreads();
    float acc = 0.f;
    #pragma unroll 8
    for (int k = 0; k < 64; k++) acc += uf[k] * Wm[k*64 + j];
    g_u2[slot*64 + j] = acc;
}

// ---------------- fused score1 + score2 + item L2 ----------------
__global__ void k_score(const int* __restrict__ user, const int* __restrict__ item,
                        const float* __restrict__ user_emb, const float* __restrict__ item_emb,
                        float* __restrict__ out) {
    int idx = blockIdx.x * blockDim.x + threadIdx.x;
    float n2 = 0.f;
    if (idx < BB*KK) {
        int b = idx / KK;
        int uid = user[b];
        int slot = g_map[uid];
        int it = item[idx];
        const float4* ue  = reinterpret_cast<const float4*>(user_emb) + (size_t)uid*16;
        const float4* u2  = reinterpret_cast<const float4*>(g_u2) + (size_t)slot*16;
        const float4* ie  = reinterpret_cast<const float4*>(item_emb) + (size_t)it*16;
        const float4* ifw = reinterpret_cast<const float4*>(g_item_featW) + (size_t)it*16;
        float s = 0.f;
        float4 ier[16];
        #pragma unroll
        for (int t = 0; t < 16; t++) {
            float4 a = ue[t], c = ie[t];
            ier[t] = c;
            s  += a.x*c.x + a.y*c.y + a.z*c.z + a.w*c.w;
            n2 += c.x*c.x + c.y*c.y + c.z*c.z + c.w*c.w;
        }
        #pragma unroll
        for (int t = 0; t < 16; t++) {
            float4 a = u2[t], c = ifw[t];
            s  += a.x*c.x + a.y*c.y + a.z*c.z + a.w*c.w;
            n2 += c.x*c.x + c.y*c.y + c.z*c.z + c.w*c.w;
        }
        float s2 = 0.f;
        #pragma unroll
        for (int r = 0; r < RREL; r++) {
            const float4* pr = reinterpret_cast<const float4*>(g_proj) + ((size_t)r*BB + slot)*32;
            const float4* ag = reinterpret_cast<const float4*>(g_item_agg + (size_t)r*IE) + (size_t)it*16;
            float dinv = 1.0f / (g_ig_deg[r*NITEMS + it] + EPSF);
            #pragma unroll
            for (int t = 0; t < 16; t++) {
                float4 a = pr[t], c = ier[t];
                s2 += a.x*c.x + a.y*c.y + a.z*c.z + a.w*c.w;
            }
            #pragma unroll
            for (int t = 0; t < 16; t++) {
                float4 a = pr[16+t], c = ag[t];
                s2 += dinv * (a.x*c.x + a.y*c.y + a.z*c.z + a.w*c.w);
            }
        }
        out[idx] = s + SCORE2_SCALE * s2;
    }
    __shared__ float red[256];
    red[threadIdx.x] = n2;
    __syncthreads();
    for (int s = 128; s > 0; s >>= 1) {
        if (threadIdx.x < s) red[threadIdx.x] += red[threadIdx.x + s];
        __syncthreads();
    }
    if (threadIdx.x == 0) atomicAdd(&g_l2i, (double)red[0]);
}

// ---------------- user-side L2 + final output element ----------------
__global__ void k_l2final(const int* __restrict__ user, const float* __restrict__ user_emb,
                          float* __restrict__ out, int out_n) {
    int b = threadIdx.x;   // 512
    int uid = user[b];
    int slot = g_map[uid];
    const float4* ue = reinterpret_cast<const float4*>(user_emb) + (size_t)uid*16;
    const float4* u2 = reinterpret_cast<const float4*>(g_u2) + (size_t)slot*16;
    float n2 = 0.f;
    #pragma unroll
    for (int t = 0; t < 16; t++) {
        float4 a = ue[t]; n2 += a.x*a.x + a.y*a.y + a.z*a.z + a.w*a.w;
        float4 c = u2[t]; n2 += c.x*c.x + c.y*c.y + c.z*c.z + c.w*c.w;
    }
    __shared__ float red[512];
    red[b] = n2;
    __syncthreads();
    for (int s = 256; s > 0; s >>= 1) {
        if (b < s) red[b] += red[b + s];
        __syncthreads();
    }
    if (b == 0 && out_n > BB*KK) {
        out[BB*KK] = (float)((double)L2C * ((double)KK * (double)red[0] + g_l2i));
    }
}

// ---------------- launch ----------------
extern "C" void kernel_launch(void* const* d_in, const int* in_sizes, int n_in,
                              void* d_out, int out_size) {
    const int*   user       = (const int*)  d_in[0];
    const int*   item       = (const int*)  d_in[1];
    const int*   rel_rows   = (const int*)  d_in[2];
    const int*   rel_cols   = (const int*)  d_in[3];
    const int*   ig_rows    = (const int*)  d_in[4];
    const int*   ig_cols    = (const int*)  d_in[5];
    const float* ig_vals    = (const float*)d_in[6];
    const int*   train_rows = (const int*)  d_in[7];
    const int*   train_cols = (const int*)  d_in[8];
    const float* user_emb   = (const float*)d_in[9];
    const float* item_emb   = (const float*)d_in[10];
    const float* mgnn       = (const float*)d_in[11];
    const float* Wb         = (const float*)d_in[12];
    const float* Wp         = (const float*)d_in[13];
    const float* Wm         = (const float*)d_in[14];
    float* out = (float*)d_out;

    k_zero<<<(RREL*IE/4 + 255)/256, 256>>>();
    k_map<<<(BB*KK + 255)/256, 256>>>(user, item);

    {
        dim3 grid((NNZ_E/4 + 255)/256, RREL);
        k_prescan_rel<<<grid, 256>>>(rel_rows, rel_cols);
    }

    {
        dim3 grid((IG_NNZ_E/4*16 + 255)/256, RREL);
        k_ig<<<grid, 256>>>(ig_rows, ig_cols, ig_vals, item_emb);
    }
    k_train_fused<<<(NNZ_E/4*16 + 255)/256, 256>>>(train_rows, train_cols, user_emb);

    k_matmul_featW<<<512, 256>>>(Wm);

    {
        dim3 grid(128, RREL);
        k_rel_heavy<<<grid, 256>>>(item_emb);
    }
    {
        dim3 grid(BB, RREL);
        k_proj<<<grid, 128>>>(Wb, Wp);
    }
    k_userW<<<BB, EMBED>>>(Wm, mgnn);

    k_score<<<(BB*KK + 255)/256, 256>>>(user, item, user_emb, item_emb, out);
    k_l2final<<<1, BB>>>(user, user_emb, out, out_size);
}